// round 1
// baseline (speedup 1.0000x reference)
#include <cuda_runtime.h>
#include <math.h>

#define MM 1024
#define NPT 128
#define AA 225
#define NSK 8

// ---------------- scratch (device globals; no allocations allowed) ----------------
__device__ __align__(16) float g_grouped[MM * AA * NSK * 5];   // 9,216,000
__device__ __align__(16) float g_v0[MM * 64 * AA];             // 14,745,600 (M,64,9,5,5)
__device__ __align__(16) float g_c1[MM * 96 * 63];             // conv1 out (M,96,7,3,3)
__device__ __align__(16) float g_c2[MM * 128 * 5];             // conv2 out (M,128,5,1,1)
__device__ __align__(16) float g_vv[MM * 64];                  // conv3 out == voxel_vec
__device__ __align__(16) float g_gx[MM * 256];                 // x @ lstm_wi + b
__device__ __align__(16) float g_wt1[1728 * 96];               // conv1 w transposed [k][oc]
__device__ __align__(16) float g_wt2[2592 * 128];              // conv2 w transposed [k][oc]
__device__ __align__(16) float g_wt3[640 * 64];                // conv3 w transposed [k][oc]

// ---------------- weight transpose ----------------
__global__ void transpose_kernel(const float* __restrict__ w1,
                                 const float* __restrict__ w2,
                                 const float* __restrict__ w3) {
    int i = blockIdx.x * blockDim.x + threadIdx.x;
    if (i < 96 * 1728)  g_wt1[(i % 1728) * 96  + (i / 1728)] = w1[i];
    if (i < 128 * 2592) g_wt2[(i % 2592) * 128 + (i / 2592)] = w2[i];
    if (i < 64 * 640)   g_wt3[(i % 640)  * 64  + (i / 640)]  = w3[i];
}

// ---------------- KNN + group ----------------
__global__ __launch_bounds__(256) void knn_group_kernel(const float* __restrict__ x,
                                                        const float* __restrict__ g_loc) {
    int m = blockIdx.x;
    __shared__ float px[NPT], py[NPT], pz[NPT], p0[NPT], p1[NPT], pn2[NPT];
    int tid = threadIdx.x;
    if (tid < NPT) {
        const float* xp = x + (m * NPT + tid) * 5;
        float a = xp[0], b = xp[1], c = xp[2];
        px[tid] = a; py[tid] = b; pz[tid] = c;
        p0[tid] = xp[3]; p1[tid] = xp[4];
        pn2[tid] = a * a + b * b + c * c;
    }
    __syncthreads();
    if (tid >= AA) return;
    int aI  = tid;
    int zi  = aI / 25, rem = aI % 25, yi = rem / 5, xi = rem % 5;
    float ax = ((float)xi - 2.0f) * 0.2f + g_loc[m * 2 + 0];
    float ay = ((float)yi - 2.0f) * 0.2f + g_loc[m * 2 + 1];
    float az = (float)zi * 0.22f + 0.1f;
    float an2 = ax * ax + ay * ay + az * az;

    float bd[NSK]; int bix[NSK];
#pragma unroll
    for (int k = 0; k < NSK; k++) { bd[k] = 3.4e38f; bix[k] = 0; }
    for (int n = 0; n < NPT; n++) {
        float d = an2 - 2.0f * (ax * px[n] + ay * py[n] + az * pz[n]) + pn2[n];
        if (d < bd[NSK - 1]) {
            float cd = d; int ci = n;
#pragma unroll
            for (int k = 0; k < NSK; k++) {
                if (cd < bd[k]) {
                    float td = bd[k]; int ti = bix[k];
                    bd[k] = cd; bix[k] = ci; cd = td; ci = ti;
                }
            }
        }
    }
    float* gp = g_grouped + (m * AA + aI) * NSK * 5;
#pragma unroll
    for (int k = 0; k < NSK; k++) {
        int n = bix[k];
        gp[k * 5 + 0] = px[n] - ax;
        gp[k * 5 + 1] = py[n] - ay;
        gp[k * 5 + 2] = pz[n] - az;
        gp[k * 5 + 3] = p0[n];
        gp[k * 5 + 4] = p1[n];
    }
}

// ---------------- PointNet MLP + attention pooling ----------------
__global__ __launch_bounds__(256) void pointnet_attn_kernel(
    const float* __restrict__ w1, const float* __restrict__ b1,
    const float* __restrict__ w2, const float* __restrict__ b2,
    const float* __restrict__ w3, const float* __restrict__ b3,
    const float* __restrict__ aw, const float* __restrict__ ab,
    float* __restrict__ out_attn) {
    __shared__ __align__(16) float sw[2824];
    float* sw1 = sw;        // 80
    float* sb1 = sw + 80;   // 16
    float* sw2 = sw + 96;   // 512
    float* sb2 = sw + 608;  // 32
    float* sw3 = sw + 640;  // 2048
    float* sb3 = sw + 2688; // 64
    float* saw = sw + 2752; // 64
    int tid = threadIdx.x;
    for (int i = tid; i < 80;   i += 256) sw1[i] = w1[i];
    for (int i = tid; i < 16;   i += 256) sb1[i] = b1[i];
    for (int i = tid; i < 512;  i += 256) sw2[i] = w2[i];
    for (int i = tid; i < 32;   i += 256) sb2[i] = b2[i];
    for (int i = tid; i < 2048; i += 256) sw3[i] = w3[i];
    for (int i = tid; i < 64;   i += 256) sb3[i] = b3[i];
    for (int i = tid; i < 64;   i += 256) saw[i] = aw[i];
    __syncthreads();
    float abv = ab[0];

    int vox = blockIdx.x * 32 + (tid >> 3);
    int k   = tid & 7;
    const float* gin = g_grouped + (vox * NSK + k) * 5;
    float i0 = gin[0], i1 = gin[1], i2 = gin[2], i3 = gin[3], i4 = gin[4];

    float h1[16];
#pragma unroll
    for (int j = 0; j < 16; j++) {
        float acc = sb1[j] + i0 * sw1[j] + i1 * sw1[16 + j] + i2 * sw1[32 + j]
                           + i3 * sw1[48 + j] + i4 * sw1[64 + j];
        h1[j] = fmaxf(acc, 0.0f);
    }
    float h2[32];
#pragma unroll
    for (int j = 0; j < 32; j += 4) {
        float4 acc = *(const float4*)&sb2[j];
#pragma unroll
        for (int i = 0; i < 16; i++) {
            float4 w = *(const float4*)&sw2[i * 32 + j];
            float h = h1[i];
            acc.x = fmaf(h, w.x, acc.x); acc.y = fmaf(h, w.y, acc.y);
            acc.z = fmaf(h, w.z, acc.z); acc.w = fmaf(h, w.w, acc.w);
        }
        h2[j]   = fmaxf(acc.x, 0.f); h2[j+1] = fmaxf(acc.y, 0.f);
        h2[j+2] = fmaxf(acc.z, 0.f); h2[j+3] = fmaxf(acc.w, 0.f);
    }
    float f[64];
#pragma unroll
    for (int j = 0; j < 64; j += 4) {
        float4 acc = *(const float4*)&sb3[j];
#pragma unroll
        for (int i = 0; i < 32; i++) {
            float4 w = *(const float4*)&sw3[i * 64 + j];
            float h = h2[i];
            acc.x = fmaf(h, w.x, acc.x); acc.y = fmaf(h, w.y, acc.y);
            acc.z = fmaf(h, w.z, acc.z); acc.w = fmaf(h, w.w, acc.w);
        }
        f[j]   = fmaxf(acc.x, 0.f); f[j+1] = fmaxf(acc.y, 0.f);
        f[j+2] = fmaxf(acc.z, 0.f); f[j+3] = fmaxf(acc.w, 0.f);
    }
    float logit = abv;
#pragma unroll
    for (int c = 0; c < 64; c++) logit = fmaf(f[c], saw[c], logit);

    // softmax over the 8 lanes of this voxel group
    float mx = logit;
    mx = fmaxf(mx, __shfl_xor_sync(0xffffffffu, mx, 1));
    mx = fmaxf(mx, __shfl_xor_sync(0xffffffffu, mx, 2));
    mx = fmaxf(mx, __shfl_xor_sync(0xffffffffu, mx, 4));
    float e = expf(logit - mx);
    float s = e;
    s += __shfl_xor_sync(0xffffffffu, s, 1);
    s += __shfl_xor_sync(0xffffffffu, s, 2);
    s += __shfl_xor_sync(0xffffffffu, s, 4);
    float attn = e / s;
    out_attn[vox * NSK + k] = attn;

    int m = vox / AA, a = vox % AA;
    float* vbase = g_v0 + (size_t)m * 64 * AA + a;
#pragma unroll
    for (int c = 0; c < 64; c++) {
        float v = f[c] * attn;
        v += __shfl_xor_sync(0xffffffffu, v, 1);
        v += __shfl_xor_sync(0xffffffffu, v, 2);
        v += __shfl_xor_sync(0xffffffffu, v, 4);
        if ((c >> 3) == k) vbase[c * AA] = v;   // static index into f/v; predicated store
    }
}

// ---------------- conv1: (M,64,9,5,5) -> (M,96,7,3,3) ----------------
__global__ __launch_bounds__(128) void conv1_kernel(const float* __restrict__ bias) {
    int m = blockIdx.x;
    __shared__ float sin[32 * 225];
    int tid = threadIdx.x;
    int ocg = tid % 12;   // oc base = ocg*8
    int spg = tid / 12;   // spatial base spg*7 (valid < 9)
    bool active = (tid < 108);

    float acc[7][8];
#pragma unroll
    for (int si = 0; si < 7; si++)
#pragma unroll
        for (int o = 0; o < 8; o++) acc[si][o] = 0.f;

    int offs[7];
#pragma unroll
    for (int si = 0; si < 7; si++) {
        int s = spg * 7 + si;
        int oz = s / 9, r = s % 9, oy = r / 3, ox = r % 3;
        offs[si] = oz * 25 + oy * 5 + ox;
    }
    const float* src = g_v0 + (size_t)m * 64 * 225;
    for (int half = 0; half < 2; half++) {
        __syncthreads();
        for (int i = tid; i < 32 * 225; i += 128) sin[i] = src[half * 32 * 225 + i];
        __syncthreads();
        if (active) {
            for (int ic2 = 0; ic2 < 32; ic2++) {
                int ic = half * 32 + ic2;
                const float* sic  = sin + ic2 * 225;
                const float* wrow = g_wt1 + ic * 27 * 96 + ocg * 8;
#pragma unroll
                for (int kz = 0; kz < 3; kz++) {
#pragma unroll
                    for (int ky = 0; ky < 3; ky++) {
#pragma unroll
                        for (int kx = 0; kx < 3; kx++) {
                            int kk = kz * 9 + ky * 3 + kx;
                            float4 wa = *(const float4*)&wrow[kk * 96];
                            float4 wb = *(const float4*)&wrow[kk * 96 + 4];
                            int ioff = kz * 25 + ky * 5 + kx;
#pragma unroll
                            for (int si = 0; si < 7; si++) {
                                float v = sic[offs[si] + ioff];
                                acc[si][0] = fmaf(v, wa.x, acc[si][0]);
                                acc[si][1] = fmaf(v, wa.y, acc[si][1]);
                                acc[si][2] = fmaf(v, wa.z, acc[si][2]);
                                acc[si][3] = fmaf(v, wa.w, acc[si][3]);
                                acc[si][4] = fmaf(v, wb.x, acc[si][4]);
                                acc[si][5] = fmaf(v, wb.y, acc[si][5]);
                                acc[si][6] = fmaf(v, wb.z, acc[si][6]);
                                acc[si][7] = fmaf(v, wb.w, acc[si][7]);
                            }
                        }
                    }
                }
            }
        }
    }
    if (active) {
#pragma unroll
        for (int o = 0; o < 8; o++) {
            int oc = ocg * 8 + o;
            float b = bias[oc];
#pragma unroll
            for (int si = 0; si < 7; si++) {
                int s = spg * 7 + si;
                g_c1[(m * 96 + oc) * 63 + s] = fmaxf(acc[si][o] + b, 0.f);
            }
        }
    }
}

// ---------------- conv2: (M,96,7,3,3) -> (M,128,5,1,1) ----------------
__global__ __launch_bounds__(64) void conv2_kernel(const float* __restrict__ bias) {
    int m = blockIdx.x;
    __shared__ float sin[96 * 63];
    int tid = threadIdx.x;
    const float* src = g_c1 + (size_t)m * 96 * 63;
    for (int i = tid; i < 96 * 63; i += 64) sin[i] = src[i];
    __syncthreads();

    float acc[2][5];
#pragma unroll
    for (int p = 0; p < 2; p++)
#pragma unroll
        for (int z = 0; z < 5; z++) acc[p][z] = 0.f;

    for (int ic = 0; ic < 96; ic++) {
        const float* sic = sin + ic * 63;
#pragma unroll
        for (int kz = 0; kz < 3; kz++) {
#pragma unroll
            for (int ky = 0; ky < 3; ky++) {
#pragma unroll
                for (int kx = 0; kx < 3; kx++) {
                    int kidx = ic * 27 + kz * 9 + ky * 3 + kx;
                    float w0  = g_wt2[kidx * 128 + tid];
                    float w1v = g_wt2[kidx * 128 + 64 + tid];
                    int ioff = ky * 3 + kx;
#pragma unroll
                    for (int z = 0; z < 5; z++) {
                        float v = sic[(z + kz) * 9 + ioff];
                        acc[0][z] = fmaf(v, w0,  acc[0][z]);
                        acc[1][z] = fmaf(v, w1v, acc[1][z]);
                    }
                }
            }
        }
    }
    float b0 = bias[tid], b1v = bias[64 + tid];
#pragma unroll
    for (int z = 0; z < 5; z++) {
        g_c2[(m * 128 + tid) * 5 + z]      = fmaxf(acc[0][z] + b0,  0.f);
        g_c2[(m * 128 + 64 + tid) * 5 + z] = fmaxf(acc[1][z] + b1v, 0.f);
    }
}

// ---------------- conv3: (M,128,5) -> (M,64) ----------------
__global__ __launch_bounds__(64) void conv3_kernel(const float* __restrict__ bias) {
    int m = blockIdx.x; int tid = threadIdx.x;
    __shared__ float sin[640];
    const float* src = g_c2 + m * 640;
    for (int i = tid; i < 640; i += 64) sin[i] = src[i];
    __syncthreads();
    float acc = 0.f;
#pragma unroll 8
    for (int i = 0; i < 640; i++) acc = fmaf(sin[i], g_wt3[i * 64 + tid], acc);
    g_vv[m * 64 + tid] = acc + bias[tid];
}

// ---------------- gates_x = voxel_vec @ Wi + b (hoisted LSTM input GEMM) ----------------
__global__ __launch_bounds__(256) void gatesx_kernel(const float* __restrict__ wi,
                                                     const float* __restrict__ b) {
    int m = blockIdx.x; int j = threadIdx.x;
    __shared__ float sv[64];
    if (j < 64) sv[j] = g_vv[m * 64 + j];
    __syncthreads();
    float acc = b[j];
#pragma unroll
    for (int i = 0; i < 64; i++) acc = fmaf(sv[i], wi[i * 256 + j], acc);
    g_gx[m * 256 + j] = acc;
}

// ---------------- LSTM scan (batch-parallel, recurrent part only) ----------------
__device__ __forceinline__ float sigmoidf_(float x) { return 1.0f / (1.0f + expf(-x)); }

__global__ __launch_bounds__(256) void lstm_kernel(const float* __restrict__ h0,
                                                   const float* __restrict__ c0,
                                                   const float* __restrict__ wh,
                                                   float* __restrict__ out_avec,
                                                   float* __restrict__ out_hn,
                                                   float* __restrict__ out_cn) {
    int b = blockIdx.x; int j = threadIdx.x;
    __shared__ float sh[64], sc[64], sg[256];
    float whreg[64];
#pragma unroll
    for (int i = 0; i < 64; i++) whreg[i] = wh[i * 256 + j];
    if (j < 64) { sh[j] = h0[b * 64 + j]; sc[j] = c0[b * 64 + j]; }
    __syncthreads();
    for (int t = 0; t < 64; t++) {
        float acc = g_gx[(b * 64 + t) * 256 + j];
#pragma unroll
        for (int i = 0; i < 64; i++) acc = fmaf(sh[i], whreg[i], acc);
        sg[j] = acc;
        __syncthreads();
        if (j < 64) {
            float ig = sigmoidf_(sg[j]);
            float fg = sigmoidf_(sg[64 + j]);
            float gg = tanhf(sg[128 + j]);
            float og = sigmoidf_(sg[192 + j]);
            float c = fg * sc[j] + ig * gg;
            float h = og * tanhf(c);
            sc[j] = c; sh[j] = h;
            out_avec[(b * 64 + t) * 64 + j] = h;
        }
        __syncthreads();
    }
    if (j < 64) { out_hn[b * 64 + j] = sh[j]; out_cn[b * 64 + j] = sc[j]; }
}

// ---------------- launch ----------------
extern "C" void kernel_launch(void* const* d_in, const int* in_sizes, int n_in,
                              void* d_out, int out_size) {
    (void)in_sizes; (void)n_in; (void)out_size;
    const float* x       = (const float*)d_in[0];
    const float* g_loc   = (const float*)d_in[1];
    const float* h0      = (const float*)d_in[2];
    const float* c0      = (const float*)d_in[3];
    const float* pn_w1   = (const float*)d_in[4];
    const float* pn_b1   = (const float*)d_in[5];
    const float* pn_w2   = (const float*)d_in[6];
    const float* pn_b2   = (const float*)d_in[7];
    const float* pn_w3   = (const float*)d_in[8];
    const float* pn_b3   = (const float*)d_in[9];
    const float* attn_w  = (const float*)d_in[10];
    const float* attn_b  = (const float*)d_in[11];
    const float* vx_w1   = (const float*)d_in[12];
    const float* vx_b1   = (const float*)d_in[13];
    const float* vx_w2   = (const float*)d_in[14];
    const float* vx_b2   = (const float*)d_in[15];
    const float* vx_w3   = (const float*)d_in[16];
    const float* vx_b3   = (const float*)d_in[17];
    const float* lstm_wi = (const float*)d_in[18];
    const float* lstm_wh = (const float*)d_in[19];
    const float* lstm_b  = (const float*)d_in[20];

    float* out      = (float*)d_out;
    float* out_avec = out;                       // 16*64*64      = 65536
    float* out_attn = out + 65536;               // 1024*225*8    = 1843200
    float* out_hn   = out + 65536 + 1843200;     // 1*16*64       = 1024
    float* out_cn   = out_hn + 1024;             // 1*16*64       = 1024

    transpose_kernel<<<1296, 256>>>(vx_w1, vx_w2, vx_w3);
    knn_group_kernel<<<1024, 256>>>(x, g_loc);
    pointnet_attn_kernel<<<7200, 256>>>(pn_w1, pn_b1, pn_w2, pn_b2, pn_w3, pn_b3,
                                        attn_w, attn_b, out_attn);
    conv1_kernel<<<1024, 128>>>(vx_b1);
    conv2_kernel<<<1024, 64>>>(vx_b2);
    conv3_kernel<<<1024, 64>>>(vx_b3);
    gatesx_kernel<<<1024, 256>>>(lstm_wi, lstm_b);
    lstm_kernel<<<16, 256>>>(h0, c0, lstm_wh, out_avec, out_hn, out_cn);
}

// round 2
// speedup vs baseline: 1.0421x; 1.0421x over previous
#include <cuda_runtime.h>
#include <math.h>

#define MM 1024
#define NPT 128
#define AA 225
#define NSK 8

// ---------------- scratch (device globals; no allocations allowed) ----------------
__device__ __align__(16) float g_grouped[MM * AA * NSK * 5];   // 9,216,000
__device__ __align__(16) float g_v0[MM * 64 * AA];             // (M,64,9,5,5)
__device__ __align__(16) float g_c1[MM * 96 * 63];             // conv1 out (M,96,7,3,3)
__device__ __align__(16) float g_c2[MM * 128 * 5];             // conv2 out (M,128,5,1,1)
__device__ __align__(16) float g_vv[MM * 64];                  // conv3 out == voxel_vec
__device__ __align__(16) float g_gx[MM * 256];                 // x @ lstm_wi + b
__device__ __align__(16) float g_wt1[1728 * 96];               // conv1 w transposed [k][oc]
__device__ __align__(16) float g_wt2[2592 * 128];              // conv2 w transposed [k][oc]
__device__ __align__(16) float g_wt3[640 * 64];                // conv3 w transposed [k][oc]

// ---------------- weight transpose ----------------
__global__ void transpose_kernel(const float* __restrict__ w1,
                                 const float* __restrict__ w2,
                                 const float* __restrict__ w3) {
    int i = blockIdx.x * blockDim.x + threadIdx.x;
    if (i < 96 * 1728)  g_wt1[(i % 1728) * 96  + (i / 1728)] = w1[i];
    if (i < 128 * 2592) g_wt2[(i % 2592) * 128 + (i / 2592)] = w2[i];
    if (i < 64 * 640)   g_wt3[(i % 640)  * 64  + (i / 640)]  = w3[i];
}

// ---------------- KNN + group ----------------
__global__ __launch_bounds__(256) void knn_group_kernel(const float* __restrict__ x,
                                                        const float* __restrict__ g_loc) {
    int m = blockIdx.x;
    __shared__ float px[NPT], py[NPT], pz[NPT], p0[NPT], p1[NPT], pn2[NPT];
    int tid = threadIdx.x;
    if (tid < NPT) {
        const float* xp = x + (m * NPT + tid) * 5;
        float a = xp[0], b = xp[1], c = xp[2];
        px[tid] = a; py[tid] = b; pz[tid] = c;
        p0[tid] = xp[3]; p1[tid] = xp[4];
        pn2[tid] = a * a + b * b + c * c;
    }
    __syncthreads();
    if (tid >= AA) return;
    int aI  = tid;
    int zi  = aI / 25, rem = aI % 25, yi = rem / 5, xi = rem % 5;
    float ax = ((float)xi - 2.0f) * 0.2f + g_loc[m * 2 + 0];
    float ay = ((float)yi - 2.0f) * 0.2f + g_loc[m * 2 + 1];
    float az = (float)zi * 0.22f + 0.1f;
    float an2 = ax * ax + ay * ay + az * az;

    float bd[NSK]; int bix[NSK];
#pragma unroll
    for (int k = 0; k < NSK; k++) { bd[k] = 3.4e38f; bix[k] = 0; }
    for (int n = 0; n < NPT; n++) {
        float d = an2 - 2.0f * (ax * px[n] + ay * py[n] + az * pz[n]) + pn2[n];
        if (d < bd[NSK - 1]) {
            float cd = d; int ci = n;
#pragma unroll
            for (int k = 0; k < NSK; k++) {
                if (cd < bd[k]) {
                    float td = bd[k]; int ti = bix[k];
                    bd[k] = cd; bix[k] = ci; cd = td; ci = ti;
                }
            }
        }
    }
    float* gp = g_grouped + (m * AA + aI) * NSK * 5;
#pragma unroll
    for (int k = 0; k < NSK; k++) {
        int n = bix[k];
        gp[k * 5 + 0] = px[n] - ax;
        gp[k * 5 + 1] = py[n] - ay;
        gp[k * 5 + 2] = pz[n] - az;
        gp[k * 5 + 3] = p0[n];
        gp[k * 5 + 4] = p1[n];
    }
}

// ---------------- PointNet MLP + attention pooling ----------------
__global__ __launch_bounds__(256) void pointnet_attn_kernel(
    const float* __restrict__ w1, const float* __restrict__ b1,
    const float* __restrict__ w2, const float* __restrict__ b2,
    const float* __restrict__ w3, const float* __restrict__ b3,
    const float* __restrict__ aw, const float* __restrict__ ab,
    float* __restrict__ out_attn) {
    __shared__ __align__(16) float sw[2824];
    float* sw1 = sw;        // 80
    float* sb1 = sw + 80;   // 16
    float* sw2 = sw + 96;   // 512
    float* sb2 = sw + 608;  // 32
    float* sw3 = sw + 640;  // 2048
    float* sb3 = sw + 2688; // 64
    float* saw = sw + 2752; // 64
    int tid = threadIdx.x;
    for (int i = tid; i < 80;   i += 256) sw1[i] = w1[i];
    for (int i = tid; i < 16;   i += 256) sb1[i] = b1[i];
    for (int i = tid; i < 512;  i += 256) sw2[i] = w2[i];
    for (int i = tid; i < 32;   i += 256) sb2[i] = b2[i];
    for (int i = tid; i < 2048; i += 256) sw3[i] = w3[i];
    for (int i = tid; i < 64;   i += 256) sb3[i] = b3[i];
    for (int i = tid; i < 64;   i += 256) saw[i] = aw[i];
    __syncthreads();
    float abv = ab[0];

    int vox = blockIdx.x * 32 + (tid >> 3);
    int k   = tid & 7;
    const float* gin = g_grouped + (vox * NSK + k) * 5;
    float i0 = gin[0], i1 = gin[1], i2 = gin[2], i3 = gin[3], i4 = gin[4];

    float h1[16];
#pragma unroll
    for (int j = 0; j < 16; j++) {
        float acc = sb1[j] + i0 * sw1[j] + i1 * sw1[16 + j] + i2 * sw1[32 + j]
                           + i3 * sw1[48 + j] + i4 * sw1[64 + j];
        h1[j] = fmaxf(acc, 0.0f);
    }
    float h2[32];
#pragma unroll
    for (int j = 0; j < 32; j += 4) {
        float4 acc = *(const float4*)&sb2[j];
#pragma unroll
        for (int i = 0; i < 16; i++) {
            float4 w = *(const float4*)&sw2[i * 32 + j];
            float h = h1[i];
            acc.x = fmaf(h, w.x, acc.x); acc.y = fmaf(h, w.y, acc.y);
            acc.z = fmaf(h, w.z, acc.z); acc.w = fmaf(h, w.w, acc.w);
        }
        h2[j]   = fmaxf(acc.x, 0.f); h2[j+1] = fmaxf(acc.y, 0.f);
        h2[j+2] = fmaxf(acc.z, 0.f); h2[j+3] = fmaxf(acc.w, 0.f);
    }
    float f[64];
#pragma unroll
    for (int j = 0; j < 64; j += 4) {
        float4 acc = *(const float4*)&sb3[j];
#pragma unroll
        for (int i = 0; i < 32; i++) {
            float4 w = *(const float4*)&sw3[i * 64 + j];
            float h = h2[i];
            acc.x = fmaf(h, w.x, acc.x); acc.y = fmaf(h, w.y, acc.y);
            acc.z = fmaf(h, w.z, acc.z); acc.w = fmaf(h, w.w, acc.w);
        }
        f[j]   = fmaxf(acc.x, 0.f); f[j+1] = fmaxf(acc.y, 0.f);
        f[j+2] = fmaxf(acc.z, 0.f); f[j+3] = fmaxf(acc.w, 0.f);
    }
    float logit = abv;
#pragma unroll
    for (int c = 0; c < 64; c++) logit = fmaf(f[c], saw[c], logit);

    // softmax over the 8 lanes of this voxel group
    float mx = logit;
    mx = fmaxf(mx, __shfl_xor_sync(0xffffffffu, mx, 1));
    mx = fmaxf(mx, __shfl_xor_sync(0xffffffffu, mx, 2));
    mx = fmaxf(mx, __shfl_xor_sync(0xffffffffu, mx, 4));
    float e = expf(logit - mx);
    float s = e;
    s += __shfl_xor_sync(0xffffffffu, s, 1);
    s += __shfl_xor_sync(0xffffffffu, s, 2);
    s += __shfl_xor_sync(0xffffffffu, s, 4);
    float attn = e / s;
    out_attn[vox * NSK + k] = attn;

    int m = vox / AA, a = vox % AA;
    float* vbase = g_v0 + (size_t)m * 64 * AA + a;
#pragma unroll
    for (int c = 0; c < 64; c++) {
        float v = f[c] * attn;
        v += __shfl_xor_sync(0xffffffffu, v, 1);
        v += __shfl_xor_sync(0xffffffffu, v, 2);
        v += __shfl_xor_sync(0xffffffffu, v, 4);
        if ((c >> 3) == k) vbase[c * AA] = v;   // static index into f/v; predicated store
    }
}

// ---------------- conv1: (M,64,9,5,5) -> (M,96,7,3,3) ----------------
// 256 threads: ocg = tid%12 (8 oc), spg = tid/12 (3 spatial). 252 active.
__global__ __launch_bounds__(256, 4) void conv1_kernel(const float* __restrict__ bias) {
    int m = blockIdx.x;
    __shared__ float sin[32 * 225];
    int tid = threadIdx.x;
    int ocg = tid % 12;
    int spg = tid / 12;           // 0..20 valid
    bool active = (tid < 252);

    float acc[3][8];
#pragma unroll
    for (int si = 0; si < 3; si++)
#pragma unroll
        for (int o = 0; o < 8; o++) acc[si][o] = 0.f;

    int offs[3];
#pragma unroll
    for (int si = 0; si < 3; si++) {
        int s = spg * 3 + si;
        if (s > 62) s = 62;
        int oz = s / 9, r = s % 9, oy = r / 3, ox = r % 3;
        offs[si] = oz * 25 + oy * 5 + ox;
    }
    const float* src = g_v0 + (size_t)m * 64 * 225;
    for (int half = 0; half < 2; half++) {
        __syncthreads();
        for (int i = tid; i < 32 * 225; i += 256) sin[i] = src[half * 32 * 225 + i];
        __syncthreads();
        if (active) {
            for (int ic2 = 0; ic2 < 32; ic2++) {
                int ic = half * 32 + ic2;
                const float* sic  = sin + ic2 * 225;
                const float* wrow = g_wt1 + ic * 27 * 96 + ocg * 8;
#pragma unroll
                for (int kz = 0; kz < 3; kz++) {
#pragma unroll
                    for (int ky = 0; ky < 3; ky++) {
#pragma unroll
                        for (int kx = 0; kx < 3; kx++) {
                            int kk = kz * 9 + ky * 3 + kx;
                            float4 wa = *(const float4*)&wrow[kk * 96];
                            float4 wb = *(const float4*)&wrow[kk * 96 + 4];
                            int ioff = kz * 25 + ky * 5 + kx;
#pragma unroll
                            for (int si = 0; si < 3; si++) {
                                float v = sic[offs[si] + ioff];
                                acc[si][0] = fmaf(v, wa.x, acc[si][0]);
                                acc[si][1] = fmaf(v, wa.y, acc[si][1]);
                                acc[si][2] = fmaf(v, wa.z, acc[si][2]);
                                acc[si][3] = fmaf(v, wa.w, acc[si][3]);
                                acc[si][4] = fmaf(v, wb.x, acc[si][4]);
                                acc[si][5] = fmaf(v, wb.y, acc[si][5]);
                                acc[si][6] = fmaf(v, wb.z, acc[si][6]);
                                acc[si][7] = fmaf(v, wb.w, acc[si][7]);
                            }
                        }
                    }
                }
            }
        }
    }
    if (active) {
#pragma unroll
        for (int o = 0; o < 8; o++) {
            int oc = ocg * 8 + o;
            float b = bias[oc];
#pragma unroll
            for (int si = 0; si < 3; si++) {
                int s = spg * 3 + si;
                g_c1[(m * 96 + oc) * 63 + s] = fmaxf(acc[si][o] + b, 0.f);
            }
        }
    }
}

// ---------------- conv2: (M,96,7,3,3) -> (M,128,5,1,1) ----------------
// Block handles 2 samples (sub = tid/64); per-thread tile 2 oc x 5 z.
__global__ __launch_bounds__(128) void conv2_kernel(const float* __restrict__ bias) {
    __shared__ float sin[2 * 96 * 63];
    int tid = threadIdx.x;
    int sub = tid >> 6;             // which sample in this block
    int t   = tid & 63;             // oc lane (oc = t and t+64)
    int m   = blockIdx.x * 2 + sub;

    const float* src = g_c1 + (size_t)blockIdx.x * 2 * 96 * 63;
    for (int i = tid; i < 2 * 96 * 63; i += 128) sin[i] = src[i];
    __syncthreads();
    const float* sbase = sin + sub * 96 * 63;

    float acc[2][5];
#pragma unroll
    for (int p = 0; p < 2; p++)
#pragma unroll
        for (int z = 0; z < 5; z++) acc[p][z] = 0.f;

    for (int ic = 0; ic < 96; ic++) {
        const float* sic = sbase + ic * 63;
#pragma unroll
        for (int kz = 0; kz < 3; kz++) {
#pragma unroll
            for (int ky = 0; ky < 3; ky++) {
#pragma unroll
                for (int kx = 0; kx < 3; kx++) {
                    int kidx = ic * 27 + kz * 9 + ky * 3 + kx;
                    float w0  = g_wt2[kidx * 128 + t];
                    float w1v = g_wt2[kidx * 128 + 64 + t];
                    int ioff = ky * 3 + kx;
#pragma unroll
                    for (int z = 0; z < 5; z++) {
                        float v = sic[(z + kz) * 9 + ioff];
                        acc[0][z] = fmaf(v, w0,  acc[0][z]);
                        acc[1][z] = fmaf(v, w1v, acc[1][z]);
                    }
                }
            }
        }
    }
    float b0 = bias[t], b1v = bias[64 + t];
#pragma unroll
    for (int z = 0; z < 5; z++) {
        g_c2[(m * 128 + t) * 5 + z]      = fmaxf(acc[0][z] + b0,  0.f);
        g_c2[(m * 128 + 64 + t) * 5 + z] = fmaxf(acc[1][z] + b1v, 0.f);
    }
}

// ---------------- conv3: (M,128,5) -> (M,64) ----------------
__global__ __launch_bounds__(64) void conv3_kernel(const float* __restrict__ bias) {
    int m = blockIdx.x; int tid = threadIdx.x;
    __shared__ float sin[640];
    const float* src = g_c2 + m * 640;
    for (int i = tid; i < 640; i += 64) sin[i] = src[i];
    __syncthreads();
    float acc = 0.f;
#pragma unroll 8
    for (int i = 0; i < 640; i++) acc = fmaf(sin[i], g_wt3[i * 64 + tid], acc);
    g_vv[m * 64 + tid] = acc + bias[tid];
}

// ---------------- gates_x = voxel_vec @ Wi + b (hoisted LSTM input GEMM) ----------------
__global__ __launch_bounds__(256) void gatesx_kernel(const float* __restrict__ wi,
                                                     const float* __restrict__ b) {
    int m = blockIdx.x; int j = threadIdx.x;
    __shared__ float sv[64];
    if (j < 64) sv[j] = g_vv[m * 64 + j];
    __syncthreads();
    float acc = b[j];
#pragma unroll
    for (int i = 0; i < 64; i++) acc = fmaf(sv[i], wi[i * 256 + j], acc);
    g_gx[m * 256 + j] = acc;
}

// ---------------- LSTM scan (batch-parallel, recurrent part only) ----------------
__device__ __forceinline__ float sigmoidf_(float x) { return 1.0f / (1.0f + expf(-x)); }

__global__ __launch_bounds__(256) void lstm_kernel(const float* __restrict__ h0,
                                                   const float* __restrict__ c0,
                                                   const float* __restrict__ wh,
                                                   float* __restrict__ out_avec,
                                                   float* __restrict__ out_hn,
                                                   float* __restrict__ out_cn) {
    int b = blockIdx.x; int j = threadIdx.x;
    __shared__ float sh[64], sc[64], sg[256];
    float whreg[64];
#pragma unroll
    for (int i = 0; i < 64; i++) whreg[i] = wh[i * 256 + j];
    if (j < 64) { sh[j] = h0[b * 64 + j]; sc[j] = c0[b * 64 + j]; }
    __syncthreads();
    for (int t = 0; t < 64; t++) {
        float acc = g_gx[(b * 64 + t) * 256 + j];
#pragma unroll
        for (int i = 0; i < 64; i++) acc = fmaf(sh[i], whreg[i], acc);
        sg[j] = acc;
        __syncthreads();
        if (j < 64) {
            float ig = sigmoidf_(sg[j]);
            float fg = sigmoidf_(sg[64 + j]);
            float gg = tanhf(sg[128 + j]);
            float og = sigmoidf_(sg[192 + j]);
            float c = fg * sc[j] + ig * gg;
            float h = og * tanhf(c);
            sc[j] = c; sh[j] = h;
            out_avec[(b * 64 + t) * 64 + j] = h;
        }
        __syncthreads();
    }
    if (j < 64) { out_hn[b * 64 + j] = sh[j]; out_cn[b * 64 + j] = sc[j]; }
}

// ---------------- launch ----------------
extern "C" void kernel_launch(void* const* d_in, const int* in_sizes, int n_in,
                              void* d_out, int out_size) {
    (void)in_sizes; (void)n_in; (void)out_size;
    const float* x       = (const float*)d_in[0];
    const float* g_loc   = (const float*)d_in[1];
    const float* h0      = (const float*)d_in[2];
    const float* c0      = (const float*)d_in[3];
    const float* pn_w1   = (const float*)d_in[4];
    const float* pn_b1   = (const float*)d_in[5];
    const float* pn_w2   = (const float*)d_in[6];
    const float* pn_b2   = (const float*)d_in[7];
    const float* pn_w3   = (const float*)d_in[8];
    const float* pn_b3   = (const float*)d_in[9];
    const float* attn_w  = (const float*)d_in[10];
    const float* attn_b  = (const float*)d_in[11];
    const float* vx_w1   = (const float*)d_in[12];
    const float* vx_b1   = (const float*)d_in[13];
    const float* vx_w2   = (const float*)d_in[14];
    const float* vx_b2   = (const float*)d_in[15];
    const float* vx_w3   = (const float*)d_in[16];
    const float* vx_b3   = (const float*)d_in[17];
    const float* lstm_wi = (const float*)d_in[18];
    const float* lstm_wh = (const float*)d_in[19];
    const float* lstm_b  = (const float*)d_in[20];

    float* out      = (float*)d_out;
    float* out_avec = out;                       // 16*64*64      = 65536
    float* out_attn = out + 65536;               // 1024*225*8    = 1843200
    float* out_hn   = out + 65536 + 1843200;     // 1*16*64       = 1024
    float* out_cn   = out_hn + 1024;             // 1*16*64       = 1024

    transpose_kernel<<<1296, 256>>>(vx_w1, vx_w2, vx_w3);
    knn_group_kernel<<<1024, 256>>>(x, g_loc);
    pointnet_attn_kernel<<<7200, 256>>>(pn_w1, pn_b1, pn_w2, pn_b2, pn_w3, pn_b3,
                                        attn_w, attn_b, out_attn);
    conv1_kernel<<<1024, 256>>>(vx_b1);
    conv2_kernel<<<512, 128>>>(vx_b2);
    conv3_kernel<<<1024, 64>>>(vx_b3);
    gatesx_kernel<<<1024, 256>>>(lstm_wi, lstm_b);
    lstm_kernel<<<16, 256>>>(h0, c0, lstm_wh, out_avec, out_hn, out_cn);
}

// round 3
// speedup vs baseline: 1.1180x; 1.0728x over previous
#include <cuda_runtime.h>
#include <math.h>

#define MM 1024
#define NPT 128
#define AA 225
#define NSK 8

typedef unsigned long long ull;

__device__ __forceinline__ ull fma2(ull a, ull b, ull c) {
    ull d;
    asm("fma.rn.f32x2 %0, %1, %2, %3;" : "=l"(d) : "l"(a), "l"(b), "l"(c));
    return d;
}
__device__ __forceinline__ ull pack2(float x, float y) {
    ull d;
    asm("mov.b64 %0, {%1, %2};" : "=l"(d) : "f"(x), "f"(y));
    return d;
}
__device__ __forceinline__ float2 unpack2(ull v) {
    float2 r;
    asm("mov.b64 {%0, %1}, %2;" : "=f"(r.x), "=f"(r.y) : "l"(v));
    return r;
}

// ---------------- scratch ----------------
__device__ __align__(16) float g_grouped[MM * AA * NSK * 5];
__device__ __align__(16) float g_v0[MM * 64 * AA];
__device__ __align__(16) float g_c1[MM * 96 * 63];
__device__ __align__(16) float g_c2[MM * 128 * 5];
__device__ __align__(16) float g_vv[MM * 64];
__device__ __align__(16) float g_gx[MM * 256];
__device__ __align__(16) float g_wt1[1728 * 96];    // [k][oc]  (oc pairs adjacent)
__device__ __align__(16) float g_wt2[2592 * 128];   // [k][pair t] interleaved (t, t+64)
__device__ __align__(16) float g_wt3[640 * 64];     // [k][oc]

// ---------------- weight transpose ----------------
__global__ void transpose_kernel(const float* __restrict__ w1,
                                 const float* __restrict__ w2,
                                 const float* __restrict__ w3) {
    int i = blockIdx.x * blockDim.x + threadIdx.x;
    if (i < 96 * 1728)  g_wt1[(i % 1728) * 96 + (i / 1728)] = w1[i];
    if (i < 128 * 2592) {
        int oc = i / 2592, k = i % 2592;
        g_wt2[k * 128 + (oc & 63) * 2 + (oc >> 6)] = w2[i];   // u64 pair = (oc t, oc t+64)
    }
    if (i < 64 * 640) g_wt3[(i % 640) * 64 + (i / 640)] = w3[i];
}

// ---------------- KNN + group ----------------
__global__ __launch_bounds__(256) void knn_group_kernel(const float* __restrict__ x,
                                                        const float* __restrict__ g_loc) {
    int m = blockIdx.x;
    __shared__ float px[NPT], py[NPT], pz[NPT], p0[NPT], p1[NPT], pn2[NPT];
    int tid = threadIdx.x;
    if (tid < NPT) {
        const float* xp = x + (m * NPT + tid) * 5;
        float a = xp[0], b = xp[1], c = xp[2];
        px[tid] = a; py[tid] = b; pz[tid] = c;
        p0[tid] = xp[3]; p1[tid] = xp[4];
        pn2[tid] = a * a + b * b + c * c;
    }
    __syncthreads();
    if (tid >= AA) return;
    int aI = tid;
    int zi = aI / 25, rem = aI % 25, yi = rem / 5, xi = rem % 5;
    float ax = ((float)xi - 2.0f) * 0.2f + g_loc[m * 2 + 0];
    float ay = ((float)yi - 2.0f) * 0.2f + g_loc[m * 2 + 1];
    float az = (float)zi * 0.22f + 0.1f;
    float an2 = ax * ax + ay * ay + az * az;

    float bd[NSK]; int bix[NSK];
#pragma unroll
    for (int k = 0; k < NSK; k++) { bd[k] = 3.4e38f; bix[k] = 0; }
    for (int n = 0; n < NPT; n++) {
        float d = an2 - 2.0f * (ax * px[n] + ay * py[n] + az * pz[n]) + pn2[n];
        if (d < bd[NSK - 1]) {
            float cd = d; int ci = n;
#pragma unroll
            for (int k = 0; k < NSK; k++) {
                if (cd < bd[k]) {
                    float td = bd[k]; int ti = bix[k];
                    bd[k] = cd; bix[k] = ci; cd = td; ci = ti;
                }
            }
        }
    }
    float* gp = g_grouped + (m * AA + aI) * NSK * 5;
#pragma unroll
    for (int k = 0; k < NSK; k++) {
        int n = bix[k];
        gp[k * 5 + 0] = px[n] - ax;
        gp[k * 5 + 1] = py[n] - ay;
        gp[k * 5 + 2] = pz[n] - az;
        gp[k * 5 + 3] = p0[n];
        gp[k * 5 + 4] = p1[n];
    }
}

// ---------------- PointNet MLP + attention pooling (FFMA2) ----------------
__global__ __launch_bounds__(256, 2) void pointnet_attn_kernel(
    const float* __restrict__ w1, const float* __restrict__ b1,
    const float* __restrict__ w2, const float* __restrict__ b2,
    const float* __restrict__ w3, const float* __restrict__ b3,
    const float* __restrict__ aw, const float* __restrict__ ab,
    float* __restrict__ out_attn) {
    __shared__ __align__(16) float sw[2824];
    float* sw1 = sw;        // 80
    float* sb1 = sw + 80;   // 16
    float* sw2 = sw + 96;   // 512
    float* sb2 = sw + 608;  // 32
    float* sw3 = sw + 640;  // 2048
    float* sb3 = sw + 2688; // 64
    float* saw = sw + 2752; // 64
    int tid = threadIdx.x;
    for (int i = tid; i < 80;   i += 256) sw1[i] = w1[i];
    for (int i = tid; i < 16;   i += 256) sb1[i] = b1[i];
    for (int i = tid; i < 512;  i += 256) sw2[i] = w2[i];
    for (int i = tid; i < 32;   i += 256) sb2[i] = b2[i];
    for (int i = tid; i < 2048; i += 256) sw3[i] = w3[i];
    for (int i = tid; i < 64;   i += 256) sb3[i] = b3[i];
    for (int i = tid; i < 64;   i += 256) saw[i] = aw[i];
    __syncthreads();
    float abv = ab[0];

    int vox = blockIdx.x * 32 + (tid >> 3);
    int k   = tid & 7;
    const float* gin = g_grouped + (vox * NSK + k) * 5;
    float i0 = gin[0], i1 = gin[1], i2 = gin[2], i3 = gin[3], i4 = gin[4];

    float h1[16];
#pragma unroll
    for (int j = 0; j < 16; j++) {
        float acc = sb1[j] + i0 * sw1[j] + i1 * sw1[16 + j] + i2 * sw1[32 + j]
                           + i3 * sw1[48 + j] + i4 * sw1[64 + j];
        h1[j] = fmaxf(acc, 0.0f);
    }
    // layer2: 16 -> 32  (16 packed pairs)
    float h2[32];
    {
        ull acc2[16];
#pragma unroll
        for (int p = 0; p < 16; p++) acc2[p] = pack2(sb2[2 * p], sb2[2 * p + 1]);
#pragma unroll
        for (int i = 0; i < 16; i++) {
            ull hh = pack2(h1[i], h1[i]);
            const float4* wr = (const float4*)&sw2[i * 32];
#pragma unroll
            for (int q = 0; q < 8; q++) {
                float4 wv = wr[q];
                ull p0 = pack2(wv.x, wv.y), p1 = pack2(wv.z, wv.w);
                acc2[2 * q]     = fma2(hh, p0, acc2[2 * q]);
                acc2[2 * q + 1] = fma2(hh, p1, acc2[2 * q + 1]);
            }
        }
#pragma unroll
        for (int p = 0; p < 16; p++) {
            float2 v = unpack2(acc2[p]);
            h2[2 * p] = fmaxf(v.x, 0.f); h2[2 * p + 1] = fmaxf(v.y, 0.f);
        }
    }
    // layer3: 32 -> 64, two halves of 32 outputs to limit live regs
    float f[64];
#pragma unroll
    for (int jh = 0; jh < 2; jh++) {
        ull acc2[16];
#pragma unroll
        for (int p = 0; p < 16; p++) acc2[p] = pack2(sb3[jh * 32 + 2 * p], sb3[jh * 32 + 2 * p + 1]);
#pragma unroll
        for (int i = 0; i < 32; i++) {
            ull hh = pack2(h2[i], h2[i]);
            const float4* wr = (const float4*)&sw3[i * 64 + jh * 32];
#pragma unroll
            for (int q = 0; q < 8; q++) {
                float4 wv = wr[q];
                ull p0 = pack2(wv.x, wv.y), p1 = pack2(wv.z, wv.w);
                acc2[2 * q]     = fma2(hh, p0, acc2[2 * q]);
                acc2[2 * q + 1] = fma2(hh, p1, acc2[2 * q + 1]);
            }
        }
#pragma unroll
        for (int p = 0; p < 16; p++) {
            float2 v = unpack2(acc2[p]);
            f[jh * 32 + 2 * p] = fmaxf(v.x, 0.f); f[jh * 32 + 2 * p + 1] = fmaxf(v.y, 0.f);
        }
    }
    float logit = abv;
#pragma unroll
    for (int c = 0; c < 64; c++) logit = fmaf(f[c], saw[c], logit);

    float mx = logit;
    mx = fmaxf(mx, __shfl_xor_sync(0xffffffffu, mx, 1));
    mx = fmaxf(mx, __shfl_xor_sync(0xffffffffu, mx, 2));
    mx = fmaxf(mx, __shfl_xor_sync(0xffffffffu, mx, 4));
    float e = expf(logit - mx);
    float s = e;
    s += __shfl_xor_sync(0xffffffffu, s, 1);
    s += __shfl_xor_sync(0xffffffffu, s, 2);
    s += __shfl_xor_sync(0xffffffffu, s, 4);
    float attn = e / s;
    out_attn[vox * NSK + k] = attn;

    int m = vox / AA, a = vox % AA;
    float* vbase = g_v0 + (size_t)m * 64 * AA + a;
#pragma unroll
    for (int c = 0; c < 64; c++) {
        float v = f[c] * attn;
        v += __shfl_xor_sync(0xffffffffu, v, 1);
        v += __shfl_xor_sync(0xffffffffu, v, 2);
        v += __shfl_xor_sync(0xffffffffu, v, 4);
        if ((c >> 3) == k) vbase[c * AA] = v;
    }
}

// ---------------- conv1: (M,64,9,5,5) -> (M,96,7,3,3) ----------------
// 192 threads = 6 warps; warp w -> oc [w*16, w*16+16) (8 u64 pairs),
// lane -> spatial {2*lane, 2*lane+1}. Warp-uniform weight LDG.128, FFMA2 math.
__global__ __launch_bounds__(192, 4) void conv1_kernel(const float* __restrict__ bias) {
    int m = blockIdx.x;
    __shared__ float sin[32 * 225];
    int tid  = threadIdx.x;
    int w    = tid >> 5;
    int lane = tid & 31;
    int s0 = lane * 2;
    int s1 = (lane == 31) ? 62 : s0 + 1;

    int oz0 = s0 / 9, r0 = s0 % 9;
    int offA = oz0 * 25 + (r0 / 3) * 5 + (r0 % 3);
    int oz1 = s1 / 9, r1 = s1 % 9;
    int offB = oz1 * 25 + (r1 / 3) * 5 + (r1 % 3);

    ull acc[2][8];
#pragma unroll
    for (int sp = 0; sp < 2; sp++)
#pragma unroll
        for (int p = 0; p < 8; p++) acc[sp][p] = 0ull;

    const float* src = g_v0 + (size_t)m * 64 * 225;
    for (int half = 0; half < 2; half++) {
        __syncthreads();
        for (int i = tid; i < 32 * 225; i += 192) sin[i] = src[half * 32 * 225 + i];
        __syncthreads();
        for (int ic2 = 0; ic2 < 32; ic2++) {
            const float* sic = sin + ic2 * 225;
            const float* wbase = g_wt1 + ((half * 32 + ic2) * 27) * 96 + w * 16;
#pragma unroll
            for (int kz = 0; kz < 3; kz++) {
#pragma unroll
                for (int ky = 0; ky < 3; ky++) {
#pragma unroll
                    for (int kx = 0; kx < 3; kx++) {
                        int kk = kz * 9 + ky * 3 + kx;
                        const ulonglong2* wp = (const ulonglong2*)(wbase + kk * 96);
                        ulonglong2 q0 = wp[0];   // pairs (0,1),(2,3)
                        ulonglong2 q1 = wp[1];   // pairs (4,5),(6,7)
                        ulonglong2 q2 = wp[2];   // pairs (8,9),(10,11)
                        ulonglong2 q3 = wp[3];   // pairs (12,13),(14,15)
                        int ioff = kz * 25 + ky * 5 + kx;
                        float vA = sic[offA + ioff];
                        float vB = sic[offB + ioff];
                        ull va = pack2(vA, vA);
                        ull vb = pack2(vB, vB);
                        acc[0][0] = fma2(va, q0.x, acc[0][0]);
                        acc[0][1] = fma2(va, q0.y, acc[0][1]);
                        acc[0][2] = fma2(va, q1.x, acc[0][2]);
                        acc[0][3] = fma2(va, q1.y, acc[0][3]);
                        acc[0][4] = fma2(va, q2.x, acc[0][4]);
                        acc[0][5] = fma2(va, q2.y, acc[0][5]);
                        acc[0][6] = fma2(va, q3.x, acc[0][6]);
                        acc[0][7] = fma2(va, q3.y, acc[0][7]);
                        acc[1][0] = fma2(vb, q0.x, acc[1][0]);
                        acc[1][1] = fma2(vb, q0.y, acc[1][1]);
                        acc[1][2] = fma2(vb, q1.x, acc[1][2]);
                        acc[1][3] = fma2(vb, q1.y, acc[1][3]);
                        acc[1][4] = fma2(vb, q2.x, acc[1][4]);
                        acc[1][5] = fma2(vb, q2.y, acc[1][5]);
                        acc[1][6] = fma2(vb, q3.x, acc[1][6]);
                        acc[1][7] = fma2(vb, q3.y, acc[1][7]);
                    }
                }
            }
        }
    }
#pragma unroll
    for (int p = 0; p < 8; p++) {
        int oc0 = w * 16 + 2 * p, oc1 = oc0 + 1;
        float b0 = bias[oc0], b1v = bias[oc1];
        float2 a0 = unpack2(acc[0][p]);
        float2 a1 = unpack2(acc[1][p]);
        g_c1[(m * 96 + oc0) * 63 + s0] = fmaxf(a0.x + b0, 0.f);
        g_c1[(m * 96 + oc1) * 63 + s0] = fmaxf(a0.y + b1v, 0.f);
        if (lane != 31) {
            g_c1[(m * 96 + oc0) * 63 + s1] = fmaxf(a1.x + b0, 0.f);
            g_c1[(m * 96 + oc1) * 63 + s1] = fmaxf(a1.y + b1v, 0.f);
        }
    }
}

// ---------------- conv2: (M,96,7,3,3) -> (M,128,5,1,1)  (FFMA2, paired oc) ---------
__global__ __launch_bounds__(128) void conv2_kernel(const float* __restrict__ bias) {
    __shared__ float sin[2 * 96 * 63];
    int tid = threadIdx.x;
    int sub = tid >> 6;
    int t   = tid & 63;             // pair lane: oc t and t+64
    int m   = blockIdx.x * 2 + sub;

    const float* src = g_c1 + (size_t)blockIdx.x * 2 * 96 * 63;
    for (int i = tid; i < 2 * 96 * 63; i += 128) sin[i] = src[i];
    __syncthreads();
    const float* sbase = sin + sub * 96 * 63;
    const ull* wt = (const ull*)g_wt2;

    ull acc[5];
#pragma unroll
    for (int z = 0; z < 5; z++) acc[z] = 0ull;

    for (int ic = 0; ic < 96; ic++) {
        const float* sic = sbase + ic * 63;
#pragma unroll
        for (int kz = 0; kz < 3; kz++) {
#pragma unroll
            for (int ky = 0; ky < 3; ky++) {
#pragma unroll
                for (int kx = 0; kx < 3; kx++) {
                    int kidx = ic * 27 + kz * 9 + ky * 3 + kx;
                    ull wp = wt[kidx * 64 + t];
                    int ioff = ky * 3 + kx;
#pragma unroll
                    for (int z = 0; z < 5; z++) {
                        float v = sic[(z + kz) * 9 + ioff];
                        acc[z] = fma2(pack2(v, v), wp, acc[z]);
                    }
                }
            }
        }
    }
    float b0 = bias[t], b1v = bias[64 + t];
#pragma unroll
    for (int z = 0; z < 5; z++) {
        float2 a = unpack2(acc[z]);
        g_c2[(m * 128 + t) * 5 + z]      = fmaxf(a.x + b0,  0.f);
        g_c2[(m * 128 + 64 + t) * 5 + z] = fmaxf(a.y + b1v, 0.f);
    }
}

// ---------------- conv3: (M,128,5) -> (M,64) ----------------
__global__ __launch_bounds__(64) void conv3_kernel(const float* __restrict__ bias) {
    int m = blockIdx.x; int tid = threadIdx.x;
    __shared__ float sin[640];
    const float* src = g_c2 + m * 640;
    for (int i = tid; i < 640; i += 64) sin[i] = src[i];
    __syncthreads();
    float acc = 0.f;
#pragma unroll 8
    for (int i = 0; i < 640; i++) acc = fmaf(sin[i], g_wt3[i * 64 + tid], acc);
    g_vv[m * 64 + tid] = acc + bias[tid];
}

// ---------------- gates_x = voxel_vec @ Wi + b ----------------
__global__ __launch_bounds__(256) void gatesx_kernel(const float* __restrict__ wi,
                                                     const float* __restrict__ b) {
    int m = blockIdx.x; int j = threadIdx.x;
    __shared__ float sv[64];
    if (j < 64) sv[j] = g_vv[m * 64 + j];
    __syncthreads();
    float acc = b[j];
#pragma unroll
    for (int i = 0; i < 64; i++) acc = fmaf(sv[i], wi[i * 256 + j], acc);
    g_gx[m * 256 + j] = acc;
}

// ---------------- LSTM scan ----------------
__device__ __forceinline__ float sigmoidf_(float x) { return 1.0f / (1.0f + expf(-x)); }

__global__ __launch_bounds__(256) void lstm_kernel(const float* __restrict__ h0,
                                                   const float* __restrict__ c0,
                                                   const float* __restrict__ wh,
                                                   float* __restrict__ out_avec,
                                                   float* __restrict__ out_hn,
                                                   float* __restrict__ out_cn) {
    int b = blockIdx.x; int j = threadIdx.x;
    __shared__ float sh[64], sc[64], sg[256];
    float whreg[64];
#pragma unroll
    for (int i = 0; i < 64; i++) whreg[i] = wh[i * 256 + j];
    if (j < 64) { sh[j] = h0[b * 64 + j]; sc[j] = c0[b * 64 + j]; }
    __syncthreads();
    for (int t = 0; t < 64; t++) {
        float acc = g_gx[(b * 64 + t) * 256 + j];
#pragma unroll
        for (int i = 0; i < 64; i++) acc = fmaf(sh[i], whreg[i], acc);
        sg[j] = acc;
        __syncthreads();
        if (j < 64) {
            float ig = sigmoidf_(sg[j]);
            float fg = sigmoidf_(sg[64 + j]);
            float gg = tanhf(sg[128 + j]);
            float og = sigmoidf_(sg[192 + j]);
            float c = fg * sc[j] + ig * gg;
            float h = og * tanhf(c);
            sc[j] = c; sh[j] = h;
            out_avec[(b * 64 + t) * 64 + j] = h;
        }
        __syncthreads();
    }
    if (j < 64) { out_hn[b * 64 + j] = sh[j]; out_cn[b * 64 + j] = sc[j]; }
}

// ---------------- launch ----------------
extern "C" void kernel_launch(void* const* d_in, const int* in_sizes, int n_in,
                              void* d_out, int out_size) {
    (void)in_sizes; (void)n_in; (void)out_size;
    const float* x       = (const float*)d_in[0];
    const float* g_loc   = (const float*)d_in[1];
    const float* h0      = (const float*)d_in[2];
    const float* c0      = (const float*)d_in[3];
    const float* pn_w1   = (const float*)d_in[4];
    const float* pn_b1   = (const float*)d_in[5];
    const float* pn_w2   = (const float*)d_in[6];
    const float* pn_b2   = (const float*)d_in[7];
    const float* pn_w3   = (const float*)d_in[8];
    const float* pn_b3   = (const float*)d_in[9];
    const float* attn_w  = (const float*)d_in[10];
    const float* attn_b  = (const float*)d_in[11];
    const float* vx_w1   = (const float*)d_in[12];
    const float* vx_b1   = (const float*)d_in[13];
    const float* vx_w2   = (const float*)d_in[14];
    const float* vx_b2   = (const float*)d_in[15];
    const float* vx_w3   = (const float*)d_in[16];
    const float* vx_b3   = (const float*)d_in[17];
    const float* lstm_wi = (const float*)d_in[18];
    const float* lstm_wh = (const float*)d_in[19];
    const float* lstm_b  = (const float*)d_in[20];

    float* out      = (float*)d_out;
    float* out_avec = out;
    float* out_attn = out + 65536;
    float* out_hn   = out + 65536 + 1843200;
    float* out_cn   = out_hn + 1024;

    transpose_kernel<<<1296, 256>>>(vx_w1, vx_w2, vx_w3);
    knn_group_kernel<<<1024, 256>>>(x, g_loc);
    pointnet_attn_kernel<<<7200, 256>>>(pn_w1, pn_b1, pn_w2, pn_b2, pn_w3, pn_b3,
                                        attn_w, attn_b, out_attn);
    conv1_kernel<<<1024, 192>>>(vx_b1);
    conv2_kernel<<<512, 128>>>(vx_b2);
    conv3_kernel<<<1024, 64>>>(vx_b3);
    gatesx_kernel<<<1024, 256>>>(lstm_wi, lstm_b);
    lstm_kernel<<<16, 256>>>(h0, c0, lstm_wh, out_avec, out_hn, out_cn);
}

// round 5
// speedup vs baseline: 1.6743x; 1.4976x over previous
#include <cuda_runtime.h>
#include <math.h>

#define MM 1024
#define NPT 128
#define AA 225
#define NSK 8

typedef unsigned long long ull;

__device__ __forceinline__ ull fma2(ull a, ull b, ull c) {
    ull d;
    asm("fma.rn.f32x2 %0, %1, %2, %3;" : "=l"(d) : "l"(a), "l"(b), "l"(c));
    return d;
}
__device__ __forceinline__ ull pack2(float x, float y) {
    ull d;
    asm("mov.b64 %0, {%1, %2};" : "=l"(d) : "f"(x), "f"(y));
    return d;
}
__device__ __forceinline__ float2 unpack2(ull v) {
    float2 r;
    asm("mov.b64 {%0, %1}, %2;" : "=f"(r.x), "=f"(r.y) : "l"(v));
    return r;
}
__device__ __forceinline__ float tf32r(float x) {
    float y;
    asm("cvt.rna.tf32.f32 %0, %1;" : "=f"(y) : "f"(x));
    return y;
}
__device__ __forceinline__ void mma_tf32(float& c0, float& c1, float& c2, float& c3,
                                         unsigned a0, unsigned a1, unsigned a2, unsigned a3,
                                         unsigned b0, unsigned b1) {
    asm volatile("mma.sync.aligned.m16n8k8.row.col.f32.tf32.tf32.f32 "
                 "{%0,%1,%2,%3}, {%4,%5,%6,%7}, {%8,%9}, {%0,%1,%2,%3};"
                 : "+f"(c0), "+f"(c1), "+f"(c2), "+f"(c3)
                 : "r"(a0), "r"(a1), "r"(a2), "r"(a3), "r"(b0), "r"(b1));
}

// ---------------- scratch ----------------
__device__ __align__(16) float g_grouped[MM * AA * NSK * 5];
__device__ __align__(16) float g_v0[MM * 64 * AA];
__device__ __align__(16) float g_c1[MM * 96 * 63];
__device__ __align__(16) float g_c2[MM * 128 * 5];
__device__ __align__(16) float g_vv[MM * 64];
__device__ __align__(16) float g_gx[MM * 256];
__device__ __align__(16) float g_wt1[1728 * 96];    // [k][oc], tf32-rounded
__device__ __align__(16) float g_wt2[2592 * 128];   // [k][pair t] interleaved (t, t+64)
__device__ __align__(16) float g_wt3[640 * 64];     // [k][oc]

// ---------------- weight transpose ----------------
__global__ void transpose_kernel(const float* __restrict__ w1,
                                 const float* __restrict__ w2,
                                 const float* __restrict__ w3) {
    int i = blockIdx.x * blockDim.x + threadIdx.x;
    if (i < 96 * 1728)  g_wt1[(i % 1728) * 96 + (i / 1728)] = tf32r(w1[i]);
    if (i < 128 * 2592) {
        int oc = i / 2592, k = i % 2592;
        g_wt2[k * 128 + (oc & 63) * 2 + (oc >> 6)] = w2[i];
    }
    if (i < 64 * 640) g_wt3[(i % 640) * 64 + (i / 640)] = w3[i];
}

// ---------------- KNN + group ----------------
__global__ __launch_bounds__(256) void knn_group_kernel(const float* __restrict__ x,
                                                        const float* __restrict__ g_loc) {
    int m = blockIdx.x;
    __shared__ float px[NPT], py[NPT], pz[NPT], p0[NPT], p1[NPT], pn2[NPT];
    int tid = threadIdx.x;
    if (tid < NPT) {
        const float* xp = x + (m * NPT + tid) * 5;
        float a = xp[0], b = xp[1], c = xp[2];
        px[tid] = a; py[tid] = b; pz[tid] = c;
        p0[tid] = xp[3]; p1[tid] = xp[4];
        pn2[tid] = a * a + b * b + c * c;
    }
    __syncthreads();
    if (tid >= AA) return;
    int aI = tid;
    int zi = aI / 25, rem = aI % 25, yi = rem / 5, xi = rem % 5;
    float ax = ((float)xi - 2.0f) * 0.2f + g_loc[m * 2 + 0];
    float ay = ((float)yi - 2.0f) * 0.2f + g_loc[m * 2 + 1];
    float az = (float)zi * 0.22f + 0.1f;
    float an2 = ax * ax + ay * ay + az * az;

    float bd[NSK]; int bix[NSK];
#pragma unroll
    for (int k = 0; k < NSK; k++) { bd[k] = 3.4e38f; bix[k] = 0; }
    for (int n = 0; n < NPT; n++) {
        float d = an2 - 2.0f * (ax * px[n] + ay * py[n] + az * pz[n]) + pn2[n];
        if (d < bd[NSK - 1]) {
            float cd = d; int ci = n;
#pragma unroll
            for (int k = 0; k < NSK; k++) {
                if (cd < bd[k]) {
                    float td = bd[k]; int ti = bix[k];
                    bd[k] = cd; bix[k] = ci; cd = td; ci = ti;
                }
            }
        }
    }
    float* gp = g_grouped + (m * AA + aI) * NSK * 5;
#pragma unroll
    for (int k = 0; k < NSK; k++) {
        int n = bix[k];
        gp[k * 5 + 0] = px[n] - ax;
        gp[k * 5 + 1] = py[n] - ay;
        gp[k * 5 + 2] = pz[n] - az;
        gp[k * 5 + 3] = p0[n];
        gp[k * 5 + 4] = p1[n];
    }
}

// ---------------- PointNet MLP + attention pooling (FFMA2) ----------------
__global__ __launch_bounds__(256, 2) void pointnet_attn_kernel(
    const float* __restrict__ w1, const float* __restrict__ b1,
    const float* __restrict__ w2, const float* __restrict__ b2,
    const float* __restrict__ w3, const float* __restrict__ b3,
    const float* __restrict__ aw, const float* __restrict__ ab,
    float* __restrict__ out_attn) {
    __shared__ __align__(16) float sw[2824];
    float* sw1 = sw;        // 80
    float* sb1 = sw + 80;   // 16
    float* sw2 = sw + 96;   // 512
    float* sb2 = sw + 608;  // 32
    float* sw3 = sw + 640;  // 2048
    float* sb3 = sw + 2688; // 64
    float* saw = sw + 2752; // 64
    int tid = threadIdx.x;
    for (int i = tid; i < 80;   i += 256) sw1[i] = w1[i];
    for (int i = tid; i < 16;   i += 256) sb1[i] = b1[i];
    for (int i = tid; i < 512;  i += 256) sw2[i] = w2[i];
    for (int i = tid; i < 32;   i += 256) sb2[i] = b2[i];
    for (int i = tid; i < 2048; i += 256) sw3[i] = w3[i];
    for (int i = tid; i < 64;   i += 256) sb3[i] = b3[i];
    for (int i = tid; i < 64;   i += 256) saw[i] = aw[i];
    __syncthreads();
    float abv = ab[0];

    int vox = blockIdx.x * 32 + (tid >> 3);
    int k   = tid & 7;
    const float* gin = g_grouped + (vox * NSK + k) * 5;
    float i0 = gin[0], i1 = gin[1], i2 = gin[2], i3 = gin[3], i4 = gin[4];

    float h1[16];
#pragma unroll
    for (int j = 0; j < 16; j++) {
        float acc = sb1[j] + i0 * sw1[j] + i1 * sw1[16 + j] + i2 * sw1[32 + j]
                           + i3 * sw1[48 + j] + i4 * sw1[64 + j];
        h1[j] = fmaxf(acc, 0.0f);
    }
    float h2[32];
    {
        ull acc2[16];
#pragma unroll
        for (int p = 0; p < 16; p++) acc2[p] = pack2(sb2[2 * p], sb2[2 * p + 1]);
#pragma unroll
        for (int i = 0; i < 16; i++) {
            ull hh = pack2(h1[i], h1[i]);
            const float4* wr = (const float4*)&sw2[i * 32];
#pragma unroll
            for (int q = 0; q < 8; q++) {
                float4 wv = wr[q];
                ull p0 = pack2(wv.x, wv.y), p1 = pack2(wv.z, wv.w);
                acc2[2 * q]     = fma2(hh, p0, acc2[2 * q]);
                acc2[2 * q + 1] = fma2(hh, p1, acc2[2 * q + 1]);
            }
        }
#pragma unroll
        for (int p = 0; p < 16; p++) {
            float2 v = unpack2(acc2[p]);
            h2[2 * p] = fmaxf(v.x, 0.f); h2[2 * p + 1] = fmaxf(v.y, 0.f);
        }
    }
    float f[64];
#pragma unroll
    for (int jh = 0; jh < 2; jh++) {
        ull acc2[16];
#pragma unroll
        for (int p = 0; p < 16; p++) acc2[p] = pack2(sb3[jh * 32 + 2 * p], sb3[jh * 32 + 2 * p + 1]);
#pragma unroll
        for (int i = 0; i < 32; i++) {
            ull hh = pack2(h2[i], h2[i]);
            const float4* wr = (const float4*)&sw3[i * 64 + jh * 32];
#pragma unroll
            for (int q = 0; q < 8; q++) {
                float4 wv = wr[q];
                ull p0 = pack2(wv.x, wv.y), p1 = pack2(wv.z, wv.w);
                acc2[2 * q]     = fma2(hh, p0, acc2[2 * q]);
                acc2[2 * q + 1] = fma2(hh, p1, acc2[2 * q + 1]);
            }
        }
#pragma unroll
        for (int p = 0; p < 16; p++) {
            float2 v = unpack2(acc2[p]);
            f[jh * 32 + 2 * p] = fmaxf(v.x, 0.f); f[jh * 32 + 2 * p + 1] = fmaxf(v.y, 0.f);
        }
    }
    float logit = abv;
#pragma unroll
    for (int c = 0; c < 64; c++) logit = fmaf(f[c], saw[c], logit);

    float mx = logit;
    mx = fmaxf(mx, __shfl_xor_sync(0xffffffffu, mx, 1));
    mx = fmaxf(mx, __shfl_xor_sync(0xffffffffu, mx, 2));
    mx = fmaxf(mx, __shfl_xor_sync(0xffffffffu, mx, 4));
    float e = expf(logit - mx);
    float s = e;
    s += __shfl_xor_sync(0xffffffffu, s, 1);
    s += __shfl_xor_sync(0xffffffffu, s, 2);
    s += __shfl_xor_sync(0xffffffffu, s, 4);
    float attn = e / s;
    out_attn[vox * NSK + k] = attn;

    int m = vox / AA, a = vox % AA;
    float* vbase = g_v0 + (size_t)m * 64 * AA + a;
#pragma unroll
    for (int c = 0; c < 64; c++) {
        float v = f[c] * attn;
        v += __shfl_xor_sync(0xffffffffu, v, 1);
        v += __shfl_xor_sync(0xffffffffu, v, 2);
        v += __shfl_xor_sync(0xffffffffu, v, 4);
        if ((c >> 3) == k) vbase[c * AA] = tf32r(v);   // tf32-rounded for conv1 MMA
    }
}

// ---------------- conv1 via implicit GEMM, mma.sync tf32 ----------------
// Per block: sample m. GEMM: D[64(s,pad), 96(oc)] = A[64, 1728] x B[1728, 96].
// 8 warps = warpM(0..3: rows 16w..16w+15) x warpN(0..1: cols 48wn..+47, 6 n8 frags).
// K processed in 2 halves of 32 ic (smem holds 32x225 input), 108 ksteps each.
__global__ __launch_bounds__(256) void conv1_kernel(const float* __restrict__ bias) {
    __shared__ float sin[32 * 225];      // 28.1 KB
    __shared__ int   ktbl[27];
    __shared__ float sbias[96];

    int m = blockIdx.x;
    int tid = threadIdx.x;
    int warp = tid >> 5;
    int lane = tid & 31;
    int g   = lane >> 2;     // groupID
    int tig = lane & 3;      // threadID in group
    int warpM = warp & 3;
    int warpN = warp >> 2;
    int nb = warpN * 48;

    if (tid < 27) {
        int kz = tid / 9, r = tid % 9, ky = r / 3, kx = r % 3;
        ktbl[tid] = kz * 25 + ky * 5 + kx;
    }
    if (tid < 96) sbias[tid] = bias[tid];

    // spatial offsets for this thread's two output rows
    int s_lo = warpM * 16 + g;          // <= 55
    int s_hi = s_lo + 8;                // <= 63
    int s_hic = (s_hi > 62) ? 62 : s_hi;
    int zlo = s_lo / 9, rlo = s_lo % 9;
    int solo = zlo * 25 + (rlo / 3) * 5 + (rlo % 3);
    int zhi = s_hic / 9, rhi = s_hic % 9;
    int sohi = zhi * 25 + (rhi / 3) * 5 + (rhi % 3);

    float acc[6][4];
#pragma unroll
    for (int f = 0; f < 6; f++)
#pragma unroll
        for (int j = 0; j < 4; j++) acc[f][j] = 0.f;

    // running B pointer: g_wt1[k*96 + n], k = 8*t + tig (+4 for b1), n = nb + f*8 + g
    const float* pB = g_wt1 + tig * 96 + nb + g;

    const float* src = g_v0 + (size_t)m * 14400;
    for (int half = 0; half < 2; half++) {
        __syncthreads();
        {
            const float4* s4 = (const float4*)(src + half * 7200);
            float4* d4 = (float4*)sin;
            for (int i = tid; i < 1800; i += 256) d4[i] = s4[i];
        }
        __syncthreads();

        int rr0 = tig, rr1 = tig + 4;
        int icoff0 = 0, icoff1 = 0;
        for (int ts = 0; ts < 108; ts++) {
            // B fragments: 6 x (b0,b1)
            unsigned bf[6][2];
#pragma unroll
            for (int f = 0; f < 6; f++) {
                bf[f][0] = __float_as_uint(pB[f * 8]);
                bf[f][1] = __float_as_uint(pB[384 + f * 8]);
            }
            pB += 768;
            // A fragment
            int a0b = icoff0 + ktbl[rr0];
            int a1b = icoff1 + ktbl[rr1];
            unsigned a0 = __float_as_uint(sin[a0b + solo]);
            unsigned a1 = __float_as_uint(sin[a0b + sohi]);
            unsigned a2 = __float_as_uint(sin[a1b + solo]);
            unsigned a3 = __float_as_uint(sin[a1b + sohi]);
            rr0 += 8; if (rr0 >= 27) { rr0 -= 27; icoff0 += 225; }
            rr1 += 8; if (rr1 >= 27) { rr1 -= 27; icoff1 += 225; }
#pragma unroll
            for (int f = 0; f < 6; f++)
                mma_tf32(acc[f][0], acc[f][1], acc[f][2], acc[f][3],
                         a0, a1, a2, a3, bf[f][0], bf[f][1]);
        }
    }

    // epilogue: D(row s, col oc) -> g_c1[(m*96+oc)*63 + s], relu(x + bias)
    float* outb = g_c1 + (size_t)m * 96 * 63;
#pragma unroll
    for (int f = 0; f < 6; f++) {
        int oc0 = nb + f * 8 + 2 * tig;
        int oc1 = oc0 + 1;
        float b0 = sbias[oc0], b1 = sbias[oc1];
        outb[oc0 * 63 + s_lo] = fmaxf(acc[f][0] + b0, 0.f);
        outb[oc1 * 63 + s_lo] = fmaxf(acc[f][1] + b1, 0.f);
        if (s_hi < 63) {
            outb[oc0 * 63 + s_hi] = fmaxf(acc[f][2] + b0, 0.f);
            outb[oc1 * 63 + s_hi] = fmaxf(acc[f][3] + b1, 0.f);
        }
    }
}

// ---------------- conv2: (M,96,7,3,3) -> (M,128,5,1,1)  (FFMA2, paired oc) ---------
__global__ __launch_bounds__(128) void conv2_kernel(const float* __restrict__ bias) {
    __shared__ float sin[2 * 96 * 63];
    int tid = threadIdx.x;
    int sub = tid >> 6;
    int t   = tid & 63;
    int m   = blockIdx.x * 2 + sub;

    const float* src = g_c1 + (size_t)blockIdx.x * 2 * 96 * 63;
    for (int i = tid; i < 2 * 96 * 63; i += 128) sin[i] = src[i];
    __syncthreads();
    const float* sbase = sin + sub * 96 * 63;
    const ull* wt = (const ull*)g_wt2;

    ull acc[5];
#pragma unroll
    for (int z = 0; z < 5; z++) acc[z] = 0ull;

    for (int ic = 0; ic < 96; ic++) {
        const float* sic = sbase + ic * 63;
#pragma unroll
        for (int kz = 0; kz < 3; kz++) {
#pragma unroll
            for (int ky = 0; ky < 3; ky++) {
#pragma unroll
                for (int kx = 0; kx < 3; kx++) {
                    int kidx = ic * 27 + kz * 9 + ky * 3 + kx;
                    ull wp = wt[kidx * 64 + t];
                    int ioff = ky * 3 + kx;
#pragma unroll
                    for (int z = 0; z < 5; z++) {
                        float v = sic[(z + kz) * 9 + ioff];
                        acc[z] = fma2(pack2(v, v), wp, acc[z]);
                    }
                }
            }
        }
    }
    float b0 = bias[t], b1v = bias[64 + t];
#pragma unroll
    for (int z = 0; z < 5; z++) {
        float2 a = unpack2(acc[z]);
        g_c2[(m * 128 + t) * 5 + z]      = fmaxf(a.x + b0,  0.f);
        g_c2[(m * 128 + 64 + t) * 5 + z] = fmaxf(a.y + b1v, 0.f);
    }
}

// ---------------- conv3: (M,128,5) -> (M,64) ----------------
__global__ __launch_bounds__(64) void conv3_kernel(const float* __restrict__ bias) {
    int m = blockIdx.x; int tid = threadIdx.x;
    __shared__ float sin[640];
    const float* src = g_c2 + m * 640;
    for (int i = tid; i < 640; i += 64) sin[i] = src[i];
    __syncthreads();
    float acc = 0.f;
#pragma unroll 8
    for (int i = 0; i < 640; i++) acc = fmaf(sin[i], g_wt3[i * 64 + tid], acc);
    g_vv[m * 64 + tid] = acc + bias[tid];
}

// ---------------- gates_x = voxel_vec @ Wi + b ----------------
__global__ __launch_bounds__(256) void gatesx_kernel(const float* __restrict__ wi,
                                                     const float* __restrict__ b) {
    int m = blockIdx.x; int j = threadIdx.x;
    __shared__ float sv[64];
    if (j < 64) sv[j] = g_vv[m * 64 + j];
    __syncthreads();
    float acc = b[j];
#pragma unroll
    for (int i = 0; i < 64; i++) acc = fmaf(sv[i], wi[i * 256 + j], acc);
    g_gx[m * 256 + j] = acc;
}

// ---------------- LSTM scan ----------------
__device__ __forceinline__ float sigmoidf_(float x) { return 1.0f / (1.0f + expf(-x)); }

__global__ __launch_bounds__(256) void lstm_kernel(const float* __restrict__ h0,
                                                   const float* __restrict__ c0,
                                                   const float* __restrict__ wh,
                                                   float* __restrict__ out_avec,
                                                   float* __restrict__ out_hn,
                                                   float* __restrict__ out_cn) {
    int b = blockIdx.x; int j = threadIdx.x;
    __shared__ float sh[64], sc[64], sg[256];
    float whreg[64];
#pragma unroll
    for (int i = 0; i < 64; i++) whreg[i] = wh[i * 256 + j];
    if (j < 64) { sh[j] = h0[b * 64 + j]; sc[j] = c0[b * 64 + j]; }
    __syncthreads();
    for (int t = 0; t < 64; t++) {
        float acc = g_gx[(b * 64 + t) * 256 + j];
#pragma unroll
        for (int i = 0; i < 64; i++) acc = fmaf(sh[i], whreg[i], acc);
        sg[j] = acc;
        __syncthreads();
        if (j < 64) {
            float ig = sigmoidf_(sg[j]);
            float fg = sigmoidf_(sg[64 + j]);
            float gg = tanhf(sg[128 + j]);
            float og = sigmoidf_(sg[192 + j]);
            float c = fg * sc[j] + ig * gg;
            float h = og * tanhf(c);
            sc[j] = c; sh[j] = h;
            out_avec[(b * 64 + t) * 64 + j] = h;
        }
        __syncthreads();
    }
    if (j < 64) { out_hn[b * 64 + j] = sh[j]; out_cn[b * 64 + j] = sc[j]; }
}

// ---------------- launch ----------------
extern "C" void kernel_launch(void* const* d_in, const int* in_sizes, int n_in,
                              void* d_out, int out_size) {
    (void)in_sizes; (void)n_in; (void)out_size;
    const float* x       = (const float*)d_in[0];
    const float* g_loc   = (const float*)d_in[1];
    const float* h0      = (const float*)d_in[2];
    const float* c0      = (const float*)d_in[3];
    const float* pn_w1   = (const float*)d_in[4];
    const float* pn_b1   = (const float*)d_in[5];
    const float* pn_w2   = (const float*)d_in[6];
    const float* pn_b2   = (const float*)d_in[7];
    const float* pn_w3   = (const float*)d_in[8];
    const float* pn_b3   = (const float*)d_in[9];
    const float* attn_w  = (const float*)d_in[10];
    const float* attn_b  = (const float*)d_in[11];
    const float* vx_w1   = (const float*)d_in[12];
    const float* vx_b1   = (const float*)d_in[13];
    const float* vx_w2   = (const float*)d_in[14];
    const float* vx_b2   = (const float*)d_in[15];
    const float* vx_w3   = (const float*)d_in[16];
    const float* vx_b3   = (const float*)d_in[17];
    const float* lstm_wi = (const float*)d_in[18];
    const float* lstm_wh = (const float*)d_in[19];
    const float* lstm_b  = (const float*)d_in[20];

    float* out      = (float*)d_out;
    float* out_avec = out;
    float* out_attn = out + 65536;
    float* out_hn   = out + 65536 + 1843200;
    float* out_cn   = out_hn + 1024;

    transpose_kernel<<<1296, 256>>>(vx_w1, vx_w2, vx_w3);
    knn_group_kernel<<<1024, 256>>>(x, g_loc);
    pointnet_attn_kernel<<<7200, 256>>>(pn_w1, pn_b1, pn_w2, pn_b2, pn_w3, pn_b3,
                                        attn_w, attn_b, out_attn);
    conv1_kernel<<<1024, 256>>>(vx_b1);
    conv2_kernel<<<512, 128>>>(vx_b2);
    conv3_kernel<<<1024, 64>>>(vx_b3);
    gatesx_kernel<<<1024, 256>>>(lstm_wi, lstm_b);
    lstm_kernel<<<16, 256>>>(h0, c0, lstm_wh, out_avec, out_hn, out_cn);
}

// round 6
// speedup vs baseline: 2.1153x; 1.2634x over previous
#include <cuda_runtime.h>
#include <math.h>

#define MM 1024
#define NPT 128
#define AA 225
#define NSK 8

typedef unsigned long long ull;

__device__ __forceinline__ ull fma2(ull a, ull b, ull c) {
    ull d;
    asm("fma.rn.f32x2 %0, %1, %2, %3;" : "=l"(d) : "l"(a), "l"(b), "l"(c));
    return d;
}
__device__ __forceinline__ ull pack2(float x, float y) {
    ull d;
    asm("mov.b64 %0, {%1, %2};" : "=l"(d) : "f"(x), "f"(y));
    return d;
}
__device__ __forceinline__ float2 unpack2(ull v) {
    float2 r;
    asm("mov.b64 {%0, %1}, %2;" : "=f"(r.x), "=f"(r.y) : "l"(v));
    return r;
}
__device__ __forceinline__ float tf32r(float x) {
    float y;
    asm("cvt.rna.tf32.f32 %0, %1;" : "=f"(y) : "f"(x));
    return y;
}
__device__ __forceinline__ void mma_tf32(float& c0, float& c1, float& c2, float& c3,
                                         unsigned a0, unsigned a1, unsigned a2, unsigned a3,
                                         unsigned b0, unsigned b1) {
    asm volatile("mma.sync.aligned.m16n8k8.row.col.f32.tf32.tf32.f32 "
                 "{%0,%1,%2,%3}, {%4,%5,%6,%7}, {%8,%9}, {%0,%1,%2,%3};"
                 : "+f"(c0), "+f"(c1), "+f"(c2), "+f"(c3)
                 : "r"(a0), "r"(a1), "r"(a2), "r"(a3), "r"(b0), "r"(b1));
}

// ---------------- scratch ----------------
__device__ __align__(16) float g_grouped[MM * AA * NSK * 5];
__device__ __align__(16) float g_v0[MM * 64 * AA];
__device__ __align__(16) float g_c1[MM * 96 * 63];
__device__ __align__(16) float g_c2[MM * 128 * 5];
__device__ __align__(16) float g_vv[MM * 64];
__device__ __align__(16) float g_gx[MM * 256];
__device__ __align__(16) float g_wb[216 * 768];     // conv1 W in MMA-fragment order
__device__ __align__(16) float g_wt2[2592 * 128];   // [k][pair t] interleaved (t, t+64)
__device__ __align__(16) float g_wt3[640 * 64];     // [k][oc]

// ---------------- weight prep ----------------
// g_wb layout: [ts][warpN][lane][12]; 12 = 6 frags x (b0,b1).
// b0 = W(k = ts*8 + tig,     oc = warpN*48 + f*8 + g)
// b1 = W(k = ts*8 + tig + 4, oc = same)
__global__ void transpose_kernel(const float* __restrict__ w1,
                                 const float* __restrict__ w2,
                                 const float* __restrict__ w3) {
    int i = blockIdx.x * blockDim.x + threadIdx.x;
    if (i < 216 * 768) {
        int ts = i / 768;
        int r  = i % 768;
        int wn = r / 384;
        int r2 = r % 384;
        int lane = r2 / 12;
        int j = r2 % 12;
        int f = j >> 1, half = j & 1;
        int g = lane >> 2, tig = lane & 3;
        int k  = ts * 8 + tig + half * 4;
        int oc = wn * 48 + f * 8 + g;
        g_wb[i] = tf32r(w1[oc * 1728 + k]);
    }
    if (i < 128 * 2592) {
        int oc = i / 2592, k = i % 2592;
        g_wt2[k * 128 + (oc & 63) * 2 + (oc >> 6)] = w2[i];
    }
    if (i < 64 * 640) g_wt3[(i % 640) * 64 + (i / 640)] = w3[i];
}

// ---------------- KNN + group ----------------
__global__ __launch_bounds__(256) void knn_group_kernel(const float* __restrict__ x,
                                                        const float* __restrict__ g_loc) {
    int m = blockIdx.x;
    __shared__ float px[NPT], py[NPT], pz[NPT], p0[NPT], p1[NPT], pn2[NPT];
    int tid = threadIdx.x;
    if (tid < NPT) {
        const float* xp = x + (m * NPT + tid) * 5;
        float a = xp[0], b = xp[1], c = xp[2];
        px[tid] = a; py[tid] = b; pz[tid] = c;
        p0[tid] = xp[3]; p1[tid] = xp[4];
        pn2[tid] = a * a + b * b + c * c;
    }
    __syncthreads();
    if (tid >= AA) return;
    int aI = tid;
    int zi = aI / 25, rem = aI % 25, yi = rem / 5, xi = rem % 5;
    float ax = ((float)xi - 2.0f) * 0.2f + g_loc[m * 2 + 0];
    float ay = ((float)yi - 2.0f) * 0.2f + g_loc[m * 2 + 1];
    float az = (float)zi * 0.22f + 0.1f;
    float an2 = ax * ax + ay * ay + az * az;

    float bd[NSK]; int bix[NSK];
#pragma unroll
    for (int k = 0; k < NSK; k++) { bd[k] = 3.4e38f; bix[k] = 0; }
    for (int n = 0; n < NPT; n++) {
        float d = an2 - 2.0f * (ax * px[n] + ay * py[n] + az * pz[n]) + pn2[n];
        if (d < bd[NSK - 1]) {
            float cd = d; int ci = n;
#pragma unroll
            for (int k = 0; k < NSK; k++) {
                if (cd < bd[k]) {
                    float td = bd[k]; int ti = bix[k];
                    bd[k] = cd; bix[k] = ci; cd = td; ci = ti;
                }
            }
        }
    }
    float* gp = g_grouped + (m * AA + aI) * NSK * 5;
#pragma unroll
    for (int k = 0; k < NSK; k++) {
        int n = bix[k];
        gp[k * 5 + 0] = px[n] - ax;
        gp[k * 5 + 1] = py[n] - ay;
        gp[k * 5 + 2] = pz[n] - az;
        gp[k * 5 + 3] = p0[n];
        gp[k * 5 + 4] = p1[n];
    }
}

// ---------------- PointNet MLP + attention pooling (FFMA2) ----------------
__global__ __launch_bounds__(256, 2) void pointnet_attn_kernel(
    const float* __restrict__ w1, const float* __restrict__ b1,
    const float* __restrict__ w2, const float* __restrict__ b2,
    const float* __restrict__ w3, const float* __restrict__ b3,
    const float* __restrict__ aw, const float* __restrict__ ab,
    float* __restrict__ out_attn) {
    __shared__ __align__(16) float sw[2824];
    float* sw1 = sw;        // 80
    float* sb1 = sw + 80;   // 16
    float* sw2 = sw + 96;   // 512
    float* sb2 = sw + 608;  // 32
    float* sw3 = sw + 640;  // 2048
    float* sb3 = sw + 2688; // 64
    float* saw = sw + 2752; // 64
    int tid = threadIdx.x;
    for (int i = tid; i < 80;   i += 256) sw1[i] = w1[i];
    for (int i = tid; i < 16;   i += 256) sb1[i] = b1[i];
    for (int i = tid; i < 512;  i += 256) sw2[i] = w2[i];
    for (int i = tid; i < 32;   i += 256) sb2[i] = b2[i];
    for (int i = tid; i < 2048; i += 256) sw3[i] = w3[i];
    for (int i = tid; i < 64;   i += 256) sb3[i] = b3[i];
    for (int i = tid; i < 64;   i += 256) saw[i] = aw[i];
    __syncthreads();
    float abv = ab[0];

    int vox = blockIdx.x * 32 + (tid >> 3);
    int k   = tid & 7;
    const float* gin = g_grouped + (vox * NSK + k) * 5;
    float i0 = gin[0], i1 = gin[1], i2 = gin[2], i3 = gin[3], i4 = gin[4];

    float h1[16];
#pragma unroll
    for (int j = 0; j < 16; j++) {
        float acc = sb1[j] + i0 * sw1[j] + i1 * sw1[16 + j] + i2 * sw1[32 + j]
                           + i3 * sw1[48 + j] + i4 * sw1[64 + j];
        h1[j] = fmaxf(acc, 0.0f);
    }
    float h2[32];
    {
        ull acc2[16];
#pragma unroll
        for (int p = 0; p < 16; p++) acc2[p] = pack2(sb2[2 * p], sb2[2 * p + 1]);
#pragma unroll
        for (int i = 0; i < 16; i++) {
            ull hh = pack2(h1[i], h1[i]);
            const float4* wr = (const float4*)&sw2[i * 32];
#pragma unroll
            for (int q = 0; q < 8; q++) {
                float4 wv = wr[q];
                ull p0 = pack2(wv.x, wv.y), p1 = pack2(wv.z, wv.w);
                acc2[2 * q]     = fma2(hh, p0, acc2[2 * q]);
                acc2[2 * q + 1] = fma2(hh, p1, acc2[2 * q + 1]);
            }
        }
#pragma unroll
        for (int p = 0; p < 16; p++) {
            float2 v = unpack2(acc2[p]);
            h2[2 * p] = fmaxf(v.x, 0.f); h2[2 * p + 1] = fmaxf(v.y, 0.f);
        }
    }
    float f[64];
#pragma unroll
    for (int jh = 0; jh < 2; jh++) {
        ull acc2[16];
#pragma unroll
        for (int p = 0; p < 16; p++) acc2[p] = pack2(sb3[jh * 32 + 2 * p], sb3[jh * 32 + 2 * p + 1]);
#pragma unroll
        for (int i = 0; i < 32; i++) {
            ull hh = pack2(h2[i], h2[i]);
            const float4* wr = (const float4*)&sw3[i * 64 + jh * 32];
#pragma unroll
            for (int q = 0; q < 8; q++) {
                float4 wv = wr[q];
                ull p0 = pack2(wv.x, wv.y), p1 = pack2(wv.z, wv.w);
                acc2[2 * q]     = fma2(hh, p0, acc2[2 * q]);
                acc2[2 * q + 1] = fma2(hh, p1, acc2[2 * q + 1]);
            }
        }
#pragma unroll
        for (int p = 0; p < 16; p++) {
            float2 v = unpack2(acc2[p]);
            f[jh * 32 + 2 * p] = fmaxf(v.x, 0.f); f[jh * 32 + 2 * p + 1] = fmaxf(v.y, 0.f);
        }
    }
    float logit = abv;
#pragma unroll
    for (int c = 0; c < 64; c++) logit = fmaf(f[c], saw[c], logit);

    float mx = logit;
    mx = fmaxf(mx, __shfl_xor_sync(0xffffffffu, mx, 1));
    mx = fmaxf(mx, __shfl_xor_sync(0xffffffffu, mx, 2));
    mx = fmaxf(mx, __shfl_xor_sync(0xffffffffu, mx, 4));
    float e = expf(logit - mx);
    float s = e;
    s += __shfl_xor_sync(0xffffffffu, s, 1);
    s += __shfl_xor_sync(0xffffffffu, s, 2);
    s += __shfl_xor_sync(0xffffffffu, s, 4);
    float attn = e / s;
    out_attn[vox * NSK + k] = attn;

    int m = vox / AA, a = vox % AA;
    float* vbase = g_v0 + (size_t)m * 64 * AA + a;
#pragma unroll
    for (int c = 0; c < 64; c++) {
        float v = f[c] * attn;
        v += __shfl_xor_sync(0xffffffffu, v, 1);
        v += __shfl_xor_sync(0xffffffffu, v, 2);
        v += __shfl_xor_sync(0xffffffffu, v, 4);
        if ((c >> 3) == k) vbase[c * AA] = tf32r(v);   // tf32-rounded for conv1 MMA
    }
}

// ---------------- conv1 via implicit GEMM, mma.sync tf32 ----------------
// Per block: sample m. GEMM: D[64(s,pad), 96(oc)] = A[64, 1728] x B[1728, 96].
// 8 warps = warpM(0..3) x warpN(0..1). B streamed from g_wb in fragment order:
// 3 coalesced LDG.128 per warp per kstep.
__global__ __launch_bounds__(256) void conv1_kernel(const float* __restrict__ bias) {
    __shared__ float sin[32 * 225];      // 28.1 KB
    __shared__ int   ktbl[27];
    __shared__ float sbias[96];

    int m = blockIdx.x;
    int tid = threadIdx.x;
    int warp = tid >> 5;
    int lane = tid & 31;
    int g   = lane >> 2;
    int tig = lane & 3;
    int warpM = warp & 3;
    int warpN = warp >> 2;
    int nb = warpN * 48;

    if (tid < 27) {
        int kz = tid / 9, r = tid % 9, ky = r / 3, kx = r % 3;
        ktbl[tid] = kz * 25 + ky * 5 + kx;
    }
    if (tid < 96) sbias[tid] = bias[tid];

    int s_lo = warpM * 16 + g;
    int s_hi = s_lo + 8;
    int s_hic = (s_hi > 62) ? 62 : s_hi;
    int zlo = s_lo / 9, rlo = s_lo % 9;
    int solo = zlo * 25 + (rlo / 3) * 5 + (rlo % 3);
    int zhi = s_hic / 9, rhi = s_hic % 9;
    int sohi = zhi * 25 + (rhi / 3) * 5 + (rhi % 3);

    float acc[6][4];
#pragma unroll
    for (int f = 0; f < 6; f++)
#pragma unroll
        for (int j = 0; j < 4; j++) acc[f][j] = 0.f;

    const float* pWB = g_wb + warpN * 384 + lane * 12;

    const float* src = g_v0 + (size_t)m * 14400;
    for (int half = 0; half < 2; half++) {
        __syncthreads();
        {
            const float4* s4 = (const float4*)(src + half * 7200);
            float4* d4 = (float4*)sin;
            for (int i = tid; i < 1800; i += 256) d4[i] = s4[i];
        }
        __syncthreads();

        int rr0 = tig, rr1 = tig + 4;
        int icoff0 = 0, icoff1 = 0;
        for (int ts = 0; ts < 108; ts++) {
            float4 q0 = *(const float4*)(pWB);
            float4 q1 = *(const float4*)(pWB + 4);
            float4 q2 = *(const float4*)(pWB + 8);
            pWB += 768;
            // A fragment
            int a0b = icoff0 + ktbl[rr0];
            int a1b = icoff1 + ktbl[rr1];
            unsigned a0 = __float_as_uint(sin[a0b + solo]);
            unsigned a1 = __float_as_uint(sin[a0b + sohi]);
            unsigned a2 = __float_as_uint(sin[a1b + solo]);
            unsigned a3 = __float_as_uint(sin[a1b + sohi]);
            rr0 += 8; if (rr0 >= 27) { rr0 -= 27; icoff0 += 225; }
            rr1 += 8; if (rr1 >= 27) { rr1 -= 27; icoff1 += 225; }
            mma_tf32(acc[0][0], acc[0][1], acc[0][2], acc[0][3], a0, a1, a2, a3,
                     __float_as_uint(q0.x), __float_as_uint(q0.y));
            mma_tf32(acc[1][0], acc[1][1], acc[1][2], acc[1][3], a0, a1, a2, a3,
                     __float_as_uint(q0.z), __float_as_uint(q0.w));
            mma_tf32(acc[2][0], acc[2][1], acc[2][2], acc[2][3], a0, a1, a2, a3,
                     __float_as_uint(q1.x), __float_as_uint(q1.y));
            mma_tf32(acc[3][0], acc[3][1], acc[3][2], acc[3][3], a0, a1, a2, a3,
                     __float_as_uint(q1.z), __float_as_uint(q1.w));
            mma_tf32(acc[4][0], acc[4][1], acc[4][2], acc[4][3], a0, a1, a2, a3,
                     __float_as_uint(q2.x), __float_as_uint(q2.y));
            mma_tf32(acc[5][0], acc[5][1], acc[5][2], acc[5][3], a0, a1, a2, a3,
                     __float_as_uint(q2.z), __float_as_uint(q2.w));
        }
    }

    float* outb = g_c1 + (size_t)m * 96 * 63;
#pragma unroll
    for (int f = 0; f < 6; f++) {
        int oc0 = nb + f * 8 + 2 * tig;
        int oc1 = oc0 + 1;
        float b0 = sbias[oc0], b1 = sbias[oc1];
        outb[oc0 * 63 + s_lo] = fmaxf(acc[f][0] + b0, 0.f);
        outb[oc1 * 63 + s_lo] = fmaxf(acc[f][1] + b1, 0.f);
        if (s_hi < 63) {
            outb[oc0 * 63 + s_hi] = fmaxf(acc[f][2] + b0, 0.f);
            outb[oc1 * 63 + s_hi] = fmaxf(acc[f][3] + b1, 0.f);
        }
    }
}

// ---------------- conv2: (M,96,7,3,3) -> (M,128,5,1,1)  (FFMA2, paired oc) ---------
__global__ __launch_bounds__(128) void conv2_kernel(const float* __restrict__ bias) {
    __shared__ float sin[2 * 96 * 63];
    int tid = threadIdx.x;
    int sub = tid >> 6;
    int t   = tid & 63;
    int m   = blockIdx.x * 2 + sub;

    const float* src = g_c1 + (size_t)blockIdx.x * 2 * 96 * 63;
    for (int i = tid; i < 2 * 96 * 63; i += 128) sin[i] = src[i];
    __syncthreads();
    const float* sbase = sin + sub * 96 * 63;
    const ull* wt = (const ull*)g_wt2;

    ull acc[5];
#pragma unroll
    for (int z = 0; z < 5; z++) acc[z] = 0ull;

    for (int ic = 0; ic < 96; ic++) {
        const float* sic = sbase + ic * 63;
#pragma unroll
        for (int kz = 0; kz < 3; kz++) {
#pragma unroll
            for (int ky = 0; ky < 3; ky++) {
#pragma unroll
                for (int kx = 0; kx < 3; kx++) {
                    int kidx = ic * 27 + kz * 9 + ky * 3 + kx;
                    ull wp = wt[kidx * 64 + t];
                    int ioff = ky * 3 + kx;
#pragma unroll
                    for (int z = 0; z < 5; z++) {
                        float v = sic[(z + kz) * 9 + ioff];
                        acc[z] = fma2(pack2(v, v), wp, acc[z]);
                    }
                }
            }
        }
    }
    float b0 = bias[t], b1v = bias[64 + t];
#pragma unroll
    for (int z = 0; z < 5; z++) {
        float2 a = unpack2(acc[z]);
        g_c2[(m * 128 + t) * 5 + z]      = fmaxf(a.x + b0,  0.f);
        g_c2[(m * 128 + 64 + t) * 5 + z] = fmaxf(a.y + b1v, 0.f);
    }
}

// ---------------- conv3: (M,128,5) -> (M,64) ----------------
__global__ __launch_bounds__(64) void conv3_kernel(const float* __restrict__ bias) {
    int m = blockIdx.x; int tid = threadIdx.x;
    __shared__ float sin[640];
    const float* src = g_c2 + m * 640;
    for (int i = tid; i < 640; i += 64) sin[i] = src[i];
    __syncthreads();
    float acc = 0.f;
#pragma unroll 8
    for (int i = 0; i < 640; i++) acc = fmaf(sin[i], g_wt3[i * 64 + tid], acc);
    g_vv[m * 64 + tid] = acc + bias[tid];
}

// ---------------- gates_x = voxel_vec @ Wi + b ----------------
__global__ __launch_bounds__(256) void gatesx_kernel(const float* __restrict__ wi,
                                                     const float* __restrict__ b) {
    int m = blockIdx.x; int j = threadIdx.x;
    __shared__ float sv[64];
    if (j < 64) sv[j] = g_vv[m * 64 + j];
    __syncthreads();
    float acc = b[j];
#pragma unroll
    for (int i = 0; i < 64; i++) acc = fmaf(sv[i], wi[i * 256 + j], acc);
    g_gx[m * 256 + j] = acc;
}

// ---------------- LSTM scan ----------------
__device__ __forceinline__ float sigmoidf_(float x) { return 1.0f / (1.0f + expf(-x)); }

__global__ __launch_bounds__(256) void lstm_kernel(const float* __restrict__ h0,
                                                   const float* __restrict__ c0,
                                                   const float* __restrict__ wh,
                                                   float* __restrict__ out_avec,
                                                   float* __restrict__ out_hn,
                                                   float* __restrict__ out_cn) {
    int b = blockIdx.x; int j = threadIdx.x;
    __shared__ float sh[64], sc[64], sg[256];
    float whreg[64];
#pragma unroll
    for (int i = 0; i < 64; i++) whreg[i] = wh[i * 256 + j];
    if (j < 64) { sh[j] = h0[b * 64 + j]; sc[j] = c0[b * 64 + j]; }
    __syncthreads();
    for (int t = 0; t < 64; t++) {
        float acc = g_gx[(b * 64 + t) * 256 + j];
#pragma unroll
        for (int i = 0; i < 64; i++) acc = fmaf(sh[i], whreg[i], acc);
        sg[j] = acc;
        __syncthreads();
        if (j < 64) {
            float ig = sigmoidf_(sg[j]);
            float fg = sigmoidf_(sg[64 + j]);
            float gg = tanhf(sg[128 + j]);
            float og = sigmoidf_(sg[192 + j]);
            float c = fg * sc[j] + ig * gg;
            float h = og * tanhf(c);
            sc[j] = c; sh[j] = h;
            out_avec[(b * 64 + t) * 64 + j] = h;
        }
        __syncthreads();
    }
    if (j < 64) { out_hn[b * 64 + j] = sh[j]; out_cn[b * 64 + j] = sc[j]; }
}

// ---------------- launch ----------------
extern "C" void kernel_launch(void* const* d_in, const int* in_sizes, int n_in,
                              void* d_out, int out_size) {
    (void)in_sizes; (void)n_in; (void)out_size;
    const float* x       = (const float*)d_in[0];
    const float* g_loc   = (const float*)d_in[1];
    const float* h0      = (const float*)d_in[2];
    const float* c0      = (const float*)d_in[3];
    const float* pn_w1   = (const float*)d_in[4];
    const float* pn_b1   = (const float*)d_in[5];
    const float* pn_w2   = (const float*)d_in[6];
    const float* pn_b2   = (const float*)d_in[7];
    const float* pn_w3   = (const float*)d_in[8];
    const float* pn_b3   = (const float*)d_in[9];
    const float* attn_w  = (const float*)d_in[10];
    const float* attn_b  = (const float*)d_in[11];
    const float* vx_w1   = (const float*)d_in[12];
    const float* vx_b1   = (const float*)d_in[13];
    const float* vx_w2   = (const float*)d_in[14];
    const float* vx_b2   = (const float*)d_in[15];
    const float* vx_w3   = (const float*)d_in[16];
    const float* vx_b3   = (const float*)d_in[17];
    const float* lstm_wi = (const float*)d_in[18];
    const float* lstm_wh = (const float*)d_in[19];
    const float* lstm_b  = (const float*)d_in[20];

    float* out      = (float*)d_out;
    float* out_avec = out;
    float* out_attn = out + 65536;
    float* out_hn   = out + 65536 + 1843200;
    float* out_cn   = out_hn + 1024;

    transpose_kernel<<<1296, 256>>>(vx_w1, vx_w2, vx_w3);
    knn_group_kernel<<<1024, 256>>>(x, g_loc);
    pointnet_attn_kernel<<<7200, 256>>>(pn_w1, pn_b1, pn_w2, pn_b2, pn_w3, pn_b3,
                                        attn_w, attn_b, out_attn);
    conv1_kernel<<<1024, 256>>>(vx_b1);
    conv2_kernel<<<512, 128>>>(vx_b2);
    conv3_kernel<<<1024, 64>>>(vx_b3);
    gatesx_kernel<<<1024, 256>>>(lstm_wi, lstm_b);
    lstm_kernel<<<16, 256>>>(h0, c0, lstm_wh, out_avec, out_hn, out_cn);
}